// round 8
// baseline (speedup 1.0000x reference)
#include <cuda_runtime.h>
#include <cuda_bf16.h>
#include <math.h>
#include <stdint.h>

// Problem constants (fixed by the reference)
#define BB 64
#define TT 512
#define FF 513
#define HH 50
#define G4 200          // 4*H
#define MROWS (BB*TT)   // 32768

#define KP1 544         // K=513 padded to 17*32
#define NKC1 17
#define KP2 64          // K=50 padded to 2*32
#define NKC2 2
#define NP1 256         // W_ih rows padded (grid.y=2)
#define NP2 640         // W_out rows padded (grid.y=5)

// Scratch (static device globals — no allocation in kernel_launch)
__device__ float g_xg[MROWS * G4];
__device__ __nv_bfloat16 g_xhi[MROWS * KP1];
__device__ __nv_bfloat16 g_xlo[MROWS * KP1];
__device__ __nv_bfloat16 g_wihhi[NP1 * KP1];
__device__ __nv_bfloat16 g_wihlo[NP1 * KP1];
__device__ __nv_bfloat16 g_hshi[MROWS * KP2];
__device__ __nv_bfloat16 g_hslo[MROWS * KP2];
__device__ __nv_bfloat16 g_wohi[NP2 * KP2];
__device__ __nv_bfloat16 g_wolo[NP2 * KP2];

// ===========================================================================
// PTX helpers
// ===========================================================================
__device__ __forceinline__ uint32_t smem_u32(const void* p) {
    uint32_t a;
    asm("{ .reg .u64 t; cvta.to.shared.u64 t, %1; cvt.u32.u64 %0, t; }"
        : "=r"(a) : "l"(p));
    return a;
}
__device__ __forceinline__ void ldsm4(uint32_t* r, uint32_t a) {
    asm volatile("ldmatrix.sync.aligned.m8n8.x4.shared.b16 {%0,%1,%2,%3}, [%4];"
                 : "=r"(r[0]), "=r"(r[1]), "=r"(r[2]), "=r"(r[3]) : "r"(a));
}
__device__ __forceinline__ void mma16816(float* c, const uint32_t* a,
                                         const uint32_t* b) {
    asm volatile(
        "mma.sync.aligned.m16n8k16.row.col.f32.bf16.bf16.f32 "
        "{%0,%1,%2,%3}, {%4,%5,%6,%7}, {%8,%9}, {%0,%1,%2,%3};"
        : "+f"(c[0]), "+f"(c[1]), "+f"(c[2]), "+f"(c[3])
        : "r"(a[0]), "r"(a[1]), "r"(a[2]), "r"(a[3]), "r"(b[0]), "r"(b[1]));
}
__device__ __forceinline__ void cpasync16(uint32_t dst, const void* src) {
    asm volatile("cp.async.cg.shared.global [%0], [%1], 16;"
                 :: "r"(dst), "l"(src));
}
#define CP_COMMIT() asm volatile("cp.async.commit_group;" ::: "memory")
#define CP_WAIT2()  asm volatile("cp.async.wait_group 2;" ::: "memory")

// ===========================================================================
// Convert fp32 (srcR x srcC) -> zero-padded bf16 hi/lo (dstR x dstC)
// ===========================================================================
__global__ void conv_split(const float* __restrict__ src,
                           __nv_bfloat16* __restrict__ hi,
                           __nv_bfloat16* __restrict__ lo,
                           int srcR, int srcC, int dstR, int dstC)
{
    int idx = blockIdx.x * blockDim.x + threadIdx.x;  // pair index
    int total = dstR * (dstC >> 1);
    if (idx >= total) return;
    int r = idx / (dstC >> 1);
    int c = (idx % (dstC >> 1)) * 2;
    float v0 = (r < srcR && c < srcC) ? src[(size_t)r * srcC + c] : 0.f;
    float v1 = (r < srcR && c + 1 < srcC) ? src[(size_t)r * srcC + c + 1] : 0.f;
    __nv_bfloat16 h0 = __float2bfloat16(v0);
    __nv_bfloat16 h1 = __float2bfloat16(v1);
    __nv_bfloat162 hv(h0, h1);
    __nv_bfloat162 lv(__float2bfloat16(v0 - __bfloat162float(h0)),
                      __float2bfloat16(v1 - __bfloat162float(h1)));
    *(__nv_bfloat162*)&hi[(size_t)r * dstC + c] = hv;
    *(__nv_bfloat162*)&lo[(size_t)r * dstC + c] = lv;
}

// ===========================================================================
// bf16 NT GEMM with bias, 3-product split expressed as ONE GEMM over a
// logical K of 3*Kp: chunk kcc -> (Ahi,Bhi), (Alo,Bhi), (Ahi,Blo).
// Block 128x128, KC=32, 4-stage cp.async pipeline (3 chunks in flight).
// 8 warps 2(m)x4(n). __launch_bounds__(256,2) -> 2 CTAs/SM.
// ===========================================================================
#define LDR 40
#define MAT_BYTES (128 * LDR * 2)        // 10240
#define STAGE_BYTES (2 * MAT_BYTES)      // 20480: A | B
#define NSTAGE 4
#define SMEM_TOTAL (NSTAGE * STAGE_BYTES) // 81920

__global__ __launch_bounds__(256, 2) void gemm_bf16_nt(
    const __nv_bfloat16* __restrict__ Ahi, const __nv_bfloat16* __restrict__ Alo,
    const __nv_bfloat16* __restrict__ Bhi, const __nv_bfloat16* __restrict__ Blo,
    const float* __restrict__ bias, float* __restrict__ C,
    int N, int Kp, int nKC)
{
    extern __shared__ __align__(16) char smem[];
    const uint32_t sbase = smem_u32(smem);

    const int tid  = threadIdx.x;
    const int lane = tid & 31;
    const int wid  = tid >> 5;
    const int wm   = wid & 1;
    const int wn   = wid >> 1;

    const int m0 = blockIdx.x * 128;
    const int n0 = blockIdx.y * 128;

    const int nKC3 = 3 * nKC;

    float acc[4][4][4];
#pragma unroll
    for (int i = 0; i < 4; ++i)
#pragma unroll
        for (int j = 0; j < 4; ++j)
#pragma unroll
            for (int q = 0; q < 4; ++q) acc[i][j][q] = 0.f;

    // issue one chunk (A tile 128x32 + B tile 128x32) into a stage.
    // 1024 x 16B cp.asyncs, 4 per thread.
    auto issue = [&](int kcc, int stage) {
        // product phase -> pointer pair + k chunk within Kp
        int kk = kcc;
        const __nv_bfloat16* Ap = Ahi;
        const __nv_bfloat16* Bp = Bhi;
        if (kcc >= 2 * nKC)      { kk = kcc - 2 * nKC; Bp = Blo; }
        else if (kcc >= nKC)     { kk = kcc - nKC;     Ap = Alo; }

        const uint32_t s32 = sbase + stage * STAGE_BYTES;
        const int kofs = kk * 32;
#pragma unroll
        for (int i = 0; i < 4; ++i) {
            const int chunk = tid + i * 256;          // 0..1023
            const int mtx = chunk >> 9;               // 0=A, 1=B
            const int c   = chunk & 511;
            const int row = c >> 2;
            const int g   = c & 3;
            const uint32_t dofs = mtx * MAT_BYTES + row * 80 + g * 16;
            const __nv_bfloat16* src =
                mtx ? (Bp + (size_t)(n0 + row) * Kp + kofs + g * 8)
                    : (Ap + (size_t)(m0 + row) * Kp + kofs + g * 8);
            cpasync16(s32 + dofs, src);
        }
    };

    // prologue: fill 3 stages
#pragma unroll
    for (int i = 0; i < 3; ++i) {
        if (i < nKC3) issue(i, i);
        CP_COMMIT();
    }

    for (int kcc = 0; kcc < nKC3; ++kcc) {
        const int cur = kcc & (NSTAGE - 1);
        CP_WAIT2();          // stage `cur` complete (3 groups in flight max)
        __syncthreads();     // data visible + prev compute of reused stage done

        if (kcc + 3 < nKC3) issue(kcc + 3, (kcc + 3) & (NSTAGE - 1));
        CP_COMMIT();         // keep group count constant (empty ok)

        const uint32_t sA = sbase + cur * STAGE_BYTES;
        const uint32_t sB = sA + MAT_BYTES;

#pragma unroll
        for (int k16 = 0; k16 < 2; ++k16) {
            const uint32_t kb = k16 * 32;

            uint32_t a[4][4];
#pragma unroll
            for (int mi = 0; mi < 4; ++mi) {
                const uint32_t off =
                    (uint32_t)(wm * 64 + mi * 16 + (lane & 15)) * 80 +
                    ((lane >> 4) * 16) + kb;
                ldsm4(a[mi], sA + off);
            }
            uint32_t b[4][2];
#pragma unroll
            for (int jj = 0; jj < 2; ++jj) {
                const uint32_t nrow =
                    (uint32_t)(wn * 32 + jj * 16 + ((lane >> 4) & 1) * 8 +
                               (lane & 7));
                const uint32_t off = nrow * 80 + (((lane >> 3) & 1) * 16) + kb;
                uint32_t t[4];
                ldsm4(t, sB + off);
                b[jj * 2][0] = t[0]; b[jj * 2][1] = t[1];
                b[jj * 2 + 1][0] = t[2]; b[jj * 2 + 1][1] = t[3];
            }
#pragma unroll
            for (int mi = 0; mi < 4; ++mi)
#pragma unroll
                for (int nj = 0; nj < 4; ++nj)
                    mma16816(acc[mi][nj], a[mi], b[nj]);
        }
    }

    // epilogue
    const int rbase = m0 + wm * 64 + (lane >> 2);
    const int cbase = n0 + wn * 32 + (lane & 3) * 2;
#pragma unroll
    for (int mi = 0; mi < 4; ++mi) {
#pragma unroll
        for (int nj = 0; nj < 4; ++nj) {
            const int col = cbase + nj * 8;
            const int row = rbase + mi * 16;
            if (col < N) {
                const float bb0 = bias[col];
                C[(size_t)row * N + col] = acc[mi][nj][0] + bb0;
                C[(size_t)(row + 8) * N + col] = acc[mi][nj][2] + bb0;
            }
            if (col + 1 < N) {
                const float bb1 = bias[col + 1];
                C[(size_t)row * N + col + 1] = acc[mi][nj][1] + bb1;
                C[(size_t)(row + 8) * N + col + 1] = acc[mi][nj][3] + bb1;
            }
        }
    }
}

// ---------------------------------------------------------------------------
// LSTM scan over batch axis. One block per t (grid 512, 256 threads).
// Writes h as bf16 hi/lo directly into GEMM2's padded A arrays.
// ---------------------------------------------------------------------------
__global__ __launch_bounds__(256) void lstm_scan(
    const float* __restrict__ W_hh, const float* __restrict__ b_hh)
{
    __shared__ __align__(16) float h_s[HH + 2];
    __shared__ float g_s[G4];

    const int t = blockIdx.x;
    const int j = threadIdx.x;

    float w[HH];
    float bj = 0.f;
    if (j < G4) {
#pragma unroll
        for (int k = 0; k < HH; ++k) w[k] = W_hh[j * HH + k];
        bj = b_hh[j];
    }
    float c = 0.f;
    if (j < HH + 2) h_s[j] = 0.f;
    __syncthreads();

    for (int b = 0; b < BB; ++b) {
        if (j < G4) {
            float g0 = g_xg[((size_t)b * TT + t) * G4 + j] + bj;
            float g1 = 0.f, g2 = 0.f, g3 = 0.f;
#pragma unroll
            for (int k = 0; k < 48; k += 4) {
                float4 hv = *(const float4*)&h_s[k];
                g0 += w[k + 0] * hv.x;
                g1 += w[k + 1] * hv.y;
                g2 += w[k + 2] * hv.z;
                g3 += w[k + 3] * hv.w;
            }
            g0 += w[48] * h_s[48];
            g1 += w[49] * h_s[49];
            g_s[j] = (g0 + g1) + (g2 + g3);
        }
        __syncthreads();
        if (j < KP2) {   // 64 threads: 50 real + 14 zero-pad cols
            float hv = 0.f;
            if (j < HH) {
                float gi = g_s[j];
                float gf = g_s[j + HH];
                float gg = g_s[j + 2 * HH];
                float go = g_s[j + 3 * HH];
                float si = 1.f / (1.f + expf(-gi));
                float sf = 1.f / (1.f + expf(-gf));
                float so = 1.f / (1.f + expf(-go));
                float tg = tanhf(gg);
                c = sf * c + si * tg;
                hv = so * tanhf(c);
                h_s[j] = hv;
            }
            __nv_bfloat16 hh = __float2bfloat16(hv);
            const size_t o = ((size_t)b * TT + t) * KP2 + j;
            g_hshi[o] = hh;
            g_hslo[o] = __float2bfloat16(hv - __bfloat162float(hh));
        }
        __syncthreads();
    }
}

// ---------------------------------------------------------------------------
extern "C" void kernel_launch(void* const* d_in, const int* in_sizes, int n_in,
                              void* d_out, int out_size)
{
    const float* x     = (const float*)d_in[0];
    const float* W_ih  = (const float*)d_in[1];
    const float* W_hh  = (const float*)d_in[2];
    const float* b_ih  = (const float*)d_in[3];
    const float* b_hh  = (const float*)d_in[4];
    const float* W_out = (const float*)d_in[5];
    const float* b_out = (const float*)d_in[6];
    float* out = (float*)d_out;

    float* xg = nullptr;
    __nv_bfloat16 *xhi, *xlo, *wihhi, *wihlo, *hshi, *hslo, *wohi, *wolo;
    cudaGetSymbolAddress((void**)&xg, g_xg);
    cudaGetSymbolAddress((void**)&xhi, g_xhi);
    cudaGetSymbolAddress((void**)&xlo, g_xlo);
    cudaGetSymbolAddress((void**)&wihhi, g_wihhi);
    cudaGetSymbolAddress((void**)&wihlo, g_wihlo);
    cudaGetSymbolAddress((void**)&hshi, g_hshi);
    cudaGetSymbolAddress((void**)&hslo, g_hslo);
    cudaGetSymbolAddress((void**)&wohi, g_wohi);
    cudaGetSymbolAddress((void**)&wolo, g_wolo);

    cudaFuncSetAttribute(gemm_bf16_nt,
                         cudaFuncAttributeMaxDynamicSharedMemorySize,
                         SMEM_TOTAL);

    // 0) conversions (hi/lo bf16, zero-padded)
    {
        int n1 = MROWS * (KP1 / 2);
        conv_split<<<(n1 + 255) / 256, 256>>>(x, xhi, xlo, MROWS, FF, MROWS, KP1);
        int n2 = NP1 * (KP1 / 2);
        conv_split<<<(n2 + 255) / 256, 256>>>(W_ih, wihhi, wihlo, G4, FF, NP1, KP1);
        int n3 = NP2 * (KP2 / 2);
        conv_split<<<(n3 + 255) / 256, 256>>>(W_out, wohi, wolo, FF, HH, NP2, KP2);
    }

    // 1) xg = x @ W_ih^T + b_ih   (M=32768, N=200, Kp=544, 51 chunks)
    {
        dim3 grid(MROWS / 128, NP1 / 128);   // (256, 2)
        gemm_bf16_nt<<<grid, 256, SMEM_TOTAL>>>(xhi, xlo, wihhi, wihlo,
                                                b_ih, xg, G4, KP1, NKC1);
    }
    // 2) LSTM scan (writes hs as bf16 hi/lo)
    lstm_scan<<<TT, 256>>>(W_hh, b_hh);

    // 3) out = hs @ W_out^T + b_out  (M=32768, N=513, Kp=64, 6 chunks)
    {
        dim3 grid(MROWS / 128, NP2 / 128);   // (256, 5)
        gemm_bf16_nt<<<grid, 256, SMEM_TOTAL>>>(hshi, hslo, wohi, wolo,
                                                b_out, out, FF, KP2, NKC2);
    }
}

// round 9
// speedup vs baseline: 1.1172x; 1.1172x over previous
#include <cuda_runtime.h>
#include <cuda_bf16.h>
#include <math.h>
#include <stdint.h>

// Problem constants (fixed by the reference)
#define BB 64
#define TT 512
#define FF 513
#define HH 50
#define G4 200          // 4*H
#define MROWS (BB*TT)   // 32768

#define KP1 544         // K=513 padded to 17*32
#define NKC1 17
#define KP2 64          // K=50 padded to 2*32
#define NKC2 2
#define NP1 256         // W_ih rows padded (grid.y=2)
#define NP2 512         // W_out rows 0..511 (col 512 via gemv)

// Scratch (static device globals — no allocation in kernel_launch)
__device__ float g_xg[MROWS * G4];
__device__ __nv_bfloat16 g_xhi[MROWS * KP1];
__device__ __nv_bfloat16 g_xlo[MROWS * KP1];
__device__ __nv_bfloat16 g_wihhi[NP1 * KP1];
__device__ __nv_bfloat16 g_wihlo[NP1 * KP1];
__device__ __nv_bfloat16 g_hshi[MROWS * KP2];
__device__ __nv_bfloat16 g_hslo[MROWS * KP2];
__device__ __nv_bfloat16 g_wohi[NP2 * KP2];
__device__ __nv_bfloat16 g_wolo[NP2 * KP2];

// ===========================================================================
// PTX helpers
// ===========================================================================
__device__ __forceinline__ uint32_t smem_u32(const void* p) {
    uint32_t a;
    asm("{ .reg .u64 t; cvta.to.shared.u64 t, %1; cvt.u32.u64 %0, t; }"
        : "=r"(a) : "l"(p));
    return a;
}
__device__ __forceinline__ void ldsm4(uint32_t* r, uint32_t a) {
    asm volatile("ldmatrix.sync.aligned.m8n8.x4.shared.b16 {%0,%1,%2,%3}, [%4];"
                 : "=r"(r[0]), "=r"(r[1]), "=r"(r[2]), "=r"(r[3]) : "r"(a));
}
__device__ __forceinline__ void mma16816(float* c, const uint32_t* a,
                                         const uint32_t* b) {
    asm volatile(
        "mma.sync.aligned.m16n8k16.row.col.f32.bf16.bf16.f32 "
        "{%0,%1,%2,%3}, {%4,%5,%6,%7}, {%8,%9}, {%0,%1,%2,%3};"
        : "+f"(c[0]), "+f"(c[1]), "+f"(c[2]), "+f"(c[3])
        : "r"(a[0]), "r"(a[1]), "r"(a[2]), "r"(a[3]), "r"(b[0]), "r"(b[1]));
}
__device__ __forceinline__ void cpasync16(uint32_t dst, const void* src) {
    asm volatile("cp.async.cg.shared.global [%0], [%1], 16;"
                 :: "r"(dst), "l"(src));
}
#define CP_COMMIT() asm volatile("cp.async.commit_group;" ::: "memory")
#define CP_WAIT0()  asm volatile("cp.async.wait_group 0;" ::: "memory")

// ===========================================================================
// Convert fp32 (srcR x srcC) -> zero-padded bf16 hi/lo (dstR x dstC).
// 8 destination elements per thread (dstC % 8 == 0), uint4 stores.
// ===========================================================================
__global__ void conv_split(const float* __restrict__ src,
                           __nv_bfloat16* __restrict__ hi,
                           __nv_bfloat16* __restrict__ lo,
                           int srcR, int srcC, int dstR, int dstC)
{
    int idx = blockIdx.x * blockDim.x + threadIdx.x;   // group of 8
    int gpr = dstC >> 3;                               // groups per row
    if (idx >= dstR * gpr) return;
    int r = idx / gpr;
    int c0 = (idx - r * gpr) * 8;

    __nv_bfloat16 hv[8], lv[8];
#pragma unroll
    for (int i = 0; i < 8; ++i) {
        int c = c0 + i;
        float v = (r < srcR && c < srcC) ? __ldg(&src[(size_t)r * srcC + c]) : 0.f;
        hv[i] = __float2bfloat16(v);
        lv[i] = __float2bfloat16(v - __bfloat162float(hv[i]));
    }
    *(uint4*)&hi[(size_t)r * dstC + c0] = *(uint4*)hv;
    *(uint4*)&lo[(size_t)r * dstC + c0] = *(uint4*)lv;
}

// ===========================================================================
// Pure-bf16 NT GEMM with bias, split accumulation (R7 design, proven):
//   C[m,n] = sum_k (Ahi+Alo)[m,k]*(Bhi+Blo)[n,k] + bias[n]   (lo*lo dropped)
// Block 128x128, KC=32, cp.async double-buffered. 8 warps 2(m)x4(n).
// __launch_bounds__(256,2): regs<=128 -> 2 CTAs/SM.
// ===========================================================================
#define LDR 40
#define MAT_BYTES (128 * LDR * 2)        // 10240
#define STAGE_BYTES (4 * MAT_BYTES)      // 40960
#define SMEM_TOTAL (2 * STAGE_BYTES)     // 81920

__global__ __launch_bounds__(256, 2) void gemm_bf16_nt(
    const __nv_bfloat16* __restrict__ Ahi, const __nv_bfloat16* __restrict__ Alo,
    const __nv_bfloat16* __restrict__ Bhi, const __nv_bfloat16* __restrict__ Blo,
    const float* __restrict__ bias, float* __restrict__ C,
    int N, int Kp, int nKC)
{
    extern __shared__ __align__(16) char smem[];
    const uint32_t sbase = smem_u32(smem);

    const int tid  = threadIdx.x;
    const int lane = tid & 31;
    const int wid  = tid >> 5;
    const int wm   = wid & 1;
    const int wn   = wid >> 1;

    const int m0 = blockIdx.x * 128;
    const int n0 = blockIdx.y * 128;

    float acc[4][4][4];
#pragma unroll
    for (int i = 0; i < 4; ++i)
#pragma unroll
        for (int j = 0; j < 4; ++j)
#pragma unroll
            for (int q = 0; q < 4; ++q) acc[i][j][q] = 0.f;

    auto issue = [&](int kc, int stage) {
        const uint32_t s32 = sbase + stage * STAGE_BYTES;
#pragma unroll
        for (int i = 0; i < 2; ++i) {
            const int chunk = tid + i * 256;      // 0..511
            const int row = chunk >> 2;
            const int g = chunk & 3;
            const uint32_t dofs = row * 80 + g * 16;
            const size_t aofs = (size_t)(m0 + row) * Kp + kc * 32 + g * 8;
            const size_t bofs = (size_t)(n0 + row) * Kp + kc * 32 + g * 8;
            cpasync16(s32 + 0 * MAT_BYTES + dofs, Ahi + aofs);
            cpasync16(s32 + 1 * MAT_BYTES + dofs, Alo + aofs);
            cpasync16(s32 + 2 * MAT_BYTES + dofs, Bhi + bofs);
            cpasync16(s32 + 3 * MAT_BYTES + dofs, Blo + bofs);
        }
    };

    issue(0, 0);
    CP_COMMIT();

    for (int kc = 0; kc < nKC; ++kc) {
        const int cur = kc & 1;
        CP_WAIT0();
        __syncthreads();

        if (kc + 1 < nKC) {
            issue(kc + 1, cur ^ 1);
            CP_COMMIT();
        }

        const uint32_t sAhi = sbase + cur * STAGE_BYTES;
        const uint32_t sAlo = sAhi + MAT_BYTES;
        const uint32_t sBhi = sAhi + 2 * MAT_BYTES;
        const uint32_t sBlo = sAhi + 3 * MAT_BYTES;

#pragma unroll
        for (int k16 = 0; k16 < 2; ++k16) {
            const uint32_t kb = k16 * 32;

            uint32_t ah[4][4], al[4][4];
#pragma unroll
            for (int mi = 0; mi < 4; ++mi) {
                const uint32_t off =
                    (uint32_t)(wm * 64 + mi * 16 + (lane & 15)) * 80 +
                    ((lane >> 4) * 16) + kb;
                ldsm4(ah[mi], sAhi + off);
                ldsm4(al[mi], sAlo + off);
            }
            uint32_t bh[4][2], bl[4][2];
#pragma unroll
            for (int jj = 0; jj < 2; ++jj) {
                const uint32_t nrow =
                    (uint32_t)(wn * 32 + jj * 16 + ((lane >> 4) & 1) * 8 +
                               (lane & 7));
                const uint32_t off = nrow * 80 + (((lane >> 3) & 1) * 16) + kb;
                uint32_t t[4];
                ldsm4(t, sBhi + off);
                bh[jj * 2][0] = t[0]; bh[jj * 2][1] = t[1];
                bh[jj * 2 + 1][0] = t[2]; bh[jj * 2 + 1][1] = t[3];
                ldsm4(t, sBlo + off);
                bl[jj * 2][0] = t[0]; bl[jj * 2][1] = t[1];
                bl[jj * 2 + 1][0] = t[2]; bl[jj * 2 + 1][1] = t[3];
            }
#pragma unroll
            for (int mi = 0; mi < 4; ++mi)
#pragma unroll
                for (int nj = 0; nj < 4; ++nj) {
                    mma16816(acc[mi][nj], ah[mi], bh[nj]);
                    mma16816(acc[mi][nj], ah[mi], bl[nj]);
                    mma16816(acc[mi][nj], al[mi], bh[nj]);
                }
        }
    }

    // epilogue
    const int rbase = m0 + wm * 64 + (lane >> 2);
    const int cbase = n0 + wn * 32 + (lane & 3) * 2;
#pragma unroll
    for (int mi = 0; mi < 4; ++mi) {
#pragma unroll
        for (int nj = 0; nj < 4; ++nj) {
            const int col = cbase + nj * 8;
            const int row = rbase + mi * 16;
            if (col < N) {
                const float bb0 = bias[col];
                C[(size_t)row * N + col] = acc[mi][nj][0] + bb0;
                C[(size_t)(row + 8) * N + col] = acc[mi][nj][2] + bb0;
            }
            if (col + 1 < N) {
                const float bb1 = bias[col + 1];
                C[(size_t)row * N + col + 1] = acc[mi][nj][1] + bb1;
                C[(size_t)(row + 8) * N + col + 1] = acc[mi][nj][3] + bb1;
            }
        }
    }
}

// ---------------------------------------------------------------------------
// Column-512 GEMV: out[m, 512] = sum_k hs[m,k] * W_out[512,k] + b_out[512]
// One warp per row; lane handles 2 k-values (bf16x2 words).
// ---------------------------------------------------------------------------
__global__ __launch_bounds__(256) void gemv_col512(
    const float* __restrict__ W_out, const float* __restrict__ b_out,
    float* __restrict__ out)
{
    const int gw = (blockIdx.x * 256 + threadIdx.x) >> 5;
    const int lane = threadIdx.x & 31;
    if (gw >= MROWS) return;

    const uint32_t hw = ((const uint32_t*)(g_hshi + (size_t)gw * KP2))[lane];
    const uint32_t lw = ((const uint32_t*)(g_hslo + (size_t)gw * KP2))[lane];
    __nv_bfloat162 h2 = *(const __nv_bfloat162*)&hw;
    __nv_bfloat162 l2 = *(const __nv_bfloat162*)&lw;
    const int k = lane * 2;
    float h0 = __bfloat162float(h2.x) + __bfloat162float(l2.x);
    float h1 = __bfloat162float(h2.y) + __bfloat162float(l2.y);
    float w0 = (k < HH) ? W_out[512 * HH + k] : 0.f;
    float w1 = (k + 1 < HH) ? W_out[512 * HH + k + 1] : 0.f;
    float s = h0 * w0 + h1 * w1;
#pragma unroll
    for (int o = 16; o > 0; o >>= 1)
        s += __shfl_down_sync(0xFFFFFFFFu, s, o);
    if (lane == 0) out[(size_t)gw * FF + 512] = s + b_out[512];
}

// ---------------------------------------------------------------------------
// LSTM scan over batch axis. One block per t (grid 512, 256 threads).
// xg for step b+1 is prefetched during step b (hides DRAM latency).
// Writes h as bf16 hi/lo directly into GEMM2's padded A arrays.
// ---------------------------------------------------------------------------
__global__ __launch_bounds__(256) void lstm_scan(
    const float* __restrict__ W_hh, const float* __restrict__ b_hh)
{
    __shared__ __align__(16) float h_s[HH + 2];
    __shared__ float g_s[G4];

    const int t = blockIdx.x;
    const int j = threadIdx.x;

    float w[HH];
    float bj = 0.f;
    if (j < G4) {
#pragma unroll
        for (int k = 0; k < HH; ++k) w[k] = W_hh[j * HH + k];
        bj = b_hh[j];
    }
    float c = 0.f;
    if (j < HH + 2) h_s[j] = 0.f;

    float pre = (j < G4) ? g_xg[(size_t)t * G4 + j] : 0.f;   // b=0
    __syncthreads();

    for (int b = 0; b < BB; ++b) {
        if (j < G4) {
            float g0 = pre + bj;
            if (b + 1 < BB)   // prefetch next step's xg (latency hidden)
                pre = g_xg[((size_t)(b + 1) * TT + t) * G4 + j];
            float g1 = 0.f, g2 = 0.f, g3 = 0.f;
#pragma unroll
            for (int k = 0; k < 48; k += 4) {
                float4 hv = *(const float4*)&h_s[k];
                g0 += w[k + 0] * hv.x;
                g1 += w[k + 1] * hv.y;
                g2 += w[k + 2] * hv.z;
                g3 += w[k + 3] * hv.w;
            }
            g0 += w[48] * h_s[48];
            g1 += w[49] * h_s[49];
            g_s[j] = (g0 + g1) + (g2 + g3);
        }
        __syncthreads();
        if (j < KP2) {   // 64 threads: 50 real + 14 zero-pad cols
            float hv = 0.f;
            if (j < HH) {
                float gi = g_s[j];
                float gf = g_s[j + HH];
                float gg = g_s[j + 2 * HH];
                float go = g_s[j + 3 * HH];
                float si = 1.f / (1.f + expf(-gi));
                float sf = 1.f / (1.f + expf(-gf));
                float so = 1.f / (1.f + expf(-go));
                float tg = tanhf(gg);
                c = sf * c + si * tg;
                hv = so * tanhf(c);
                h_s[j] = hv;
            }
            __nv_bfloat16 hh = __float2bfloat16(hv);
            const size_t o = ((size_t)b * TT + t) * KP2 + j;
            g_hshi[o] = hh;
            g_hslo[o] = __float2bfloat16(hv - __bfloat162float(hh));
        }
        __syncthreads();
    }
}

// ---------------------------------------------------------------------------
extern "C" void kernel_launch(void* const* d_in, const int* in_sizes, int n_in,
                              void* d_out, int out_size)
{
    const float* x     = (const float*)d_in[0];
    const float* W_ih  = (const float*)d_in[1];
    const float* W_hh  = (const float*)d_in[2];
    const float* b_ih  = (const float*)d_in[3];
    const float* b_hh  = (const float*)d_in[4];
    const float* W_out = (const float*)d_in[5];
    const float* b_out = (const float*)d_in[6];
    float* out = (float*)d_out;

    float* xg = nullptr;
    __nv_bfloat16 *xhi, *xlo, *wihhi, *wihlo, *hshi, *hslo, *wohi, *wolo;
    cudaGetSymbolAddress((void**)&xg, g_xg);
    cudaGetSymbolAddress((void**)&xhi, g_xhi);
    cudaGetSymbolAddress((void**)&xlo, g_xlo);
    cudaGetSymbolAddress((void**)&wihhi, g_wihhi);
    cudaGetSymbolAddress((void**)&wihlo, g_wihlo);
    cudaGetSymbolAddress((void**)&hshi, g_hshi);
    cudaGetSymbolAddress((void**)&hslo, g_hslo);
    cudaGetSymbolAddress((void**)&wohi, g_wohi);
    cudaGetSymbolAddress((void**)&wolo, g_wolo);

    cudaFuncSetAttribute(gemm_bf16_nt,
                         cudaFuncAttributeMaxDynamicSharedMemorySize,
                         SMEM_TOTAL);

    // 0) conversions (hi/lo bf16, zero-padded)
    {
        int n1 = MROWS * (KP1 / 8);
        conv_split<<<(n1 + 255) / 256, 256>>>(x, xhi, xlo, MROWS, FF, MROWS, KP1);
        int n2 = NP1 * (KP1 / 8);
        conv_split<<<(n2 + 255) / 256, 256>>>(W_ih, wihhi, wihlo, G4, FF, NP1, KP1);
        int n3 = NP2 * (KP2 / 8);
        conv_split<<<(n3 + 255) / 256, 256>>>(W_out, wohi, wolo, FF, HH, NP2, KP2);
    }

    // 1) xg = x @ W_ih^T + b_ih   (M=32768, N=200, Kp=544)
    {
        dim3 grid(MROWS / 128, NP1 / 128);   // (256, 2)
        gemm_bf16_nt<<<grid, 256, SMEM_TOTAL>>>(xhi, xlo, wihhi, wihlo,
                                                b_ih, xg, G4, KP1, NKC1);
    }
    // 2) LSTM scan (writes hs as bf16 hi/lo)
    lstm_scan<<<TT, 256>>>(W_hh, b_hh);

    // 3) out[:, 0:512] = hs @ W_out[0:512]^T + b_out  (grid.y=4, no padding waste)
    {
        dim3 grid(MROWS / 128, NP2 / 128);   // (256, 4)
        gemm_bf16_nt<<<grid, 256, SMEM_TOTAL>>>(hshi, hslo, wohi, wolo,
                                                b_out, out, FF, KP2, NKC2);
    }
    // 3b) out[:, 512] via warp-per-row GEMV
    gemv_col512<<<MROWS / 8, 256>>>(W_out, b_out, out);
}

// round 10
// speedup vs baseline: 1.1534x; 1.0324x over previous
#include <cuda_runtime.h>
#include <cuda_bf16.h>
#include <math.h>
#include <stdint.h>

// Problem constants (fixed by the reference)
#define BB 64
#define TT 512
#define FF 513
#define HH 50
#define G4 200          // 4*H
#define MROWS (BB*TT)   // 32768

#define KP1 544         // K=513 padded to 17*32
#define NKC1 17
#define KP2 64          // K=50 padded to 2*32
#define NKC2 2
#define NP1 256         // W_ih rows padded (grid.y=2)
#define NP2 512         // W_out rows 0..511 (col 512 via gemv)
#define XGS 256         // xg row stride (padded for aligned float4 stores)

// Scratch (static device globals — no allocation in kernel_launch)
__device__ float g_xg[MROWS * XGS];
__device__ __nv_bfloat16 g_xhi[MROWS * KP1];
__device__ __nv_bfloat16 g_xlo[MROWS * KP1];
__device__ __nv_bfloat16 g_wihhi[NP1 * KP1];
__device__ __nv_bfloat16 g_wihlo[NP1 * KP1];
__device__ __nv_bfloat16 g_hshi[MROWS * KP2];
__device__ __nv_bfloat16 g_hslo[MROWS * KP2];
__device__ __nv_bfloat16 g_wohi[NP2 * KP2];
__device__ __nv_bfloat16 g_wolo[NP2 * KP2];

// ===========================================================================
// PTX helpers
// ===========================================================================
__device__ __forceinline__ uint32_t smem_u32(const void* p) {
    uint32_t a;
    asm("{ .reg .u64 t; cvta.to.shared.u64 t, %1; cvt.u32.u64 %0, t; }"
        : "=r"(a) : "l"(p));
    return a;
}
__device__ __forceinline__ void ldsm4(uint32_t* r, uint32_t a) {
    asm volatile("ldmatrix.sync.aligned.m8n8.x4.shared.b16 {%0,%1,%2,%3}, [%4];"
                 : "=r"(r[0]), "=r"(r[1]), "=r"(r[2]), "=r"(r[3]) : "r"(a));
}
__device__ __forceinline__ void mma16816(float* c, const uint32_t* a,
                                         const uint32_t* b) {
    asm volatile(
        "mma.sync.aligned.m16n8k16.row.col.f32.bf16.bf16.f32 "
        "{%0,%1,%2,%3}, {%4,%5,%6,%7}, {%8,%9}, {%0,%1,%2,%3};"
        : "+f"(c[0]), "+f"(c[1]), "+f"(c[2]), "+f"(c[3])
        : "r"(a[0]), "r"(a[1]), "r"(a[2]), "r"(a[3]), "r"(b[0]), "r"(b[1]));
}
__device__ __forceinline__ void cpasync16(uint32_t dst, const void* src) {
    asm volatile("cp.async.cg.shared.global [%0], [%1], 16;"
                 :: "r"(dst), "l"(src));
}
#define CP_COMMIT() asm volatile("cp.async.commit_group;" ::: "memory")
#define CP_WAIT0()  asm volatile("cp.async.wait_group 0;" ::: "memory")

// ===========================================================================
// Merged conversion kernel: fp32 -> zero-padded bf16 hi/lo, 3 tensors.
// 8 destination elements per thread, uint4 stores.
// ===========================================================================
#define NB_X   (MROWS * (KP1/8) / 256)              // 8704
#define NB_WIH ((NP1 * (KP1/8) + 255) / 256)        // 68
#define NB_WO  ((NP2 * (KP2/8) + 255) / 256)        // 16

__device__ __forceinline__ void conv_body(
    const float* __restrict__ src, __nv_bfloat16* __restrict__ hi,
    __nv_bfloat16* __restrict__ lo, int srcR, int srcC, int dstR, int dstC,
    int idx)
{
    int gpr = dstC >> 3;
    if (idx >= dstR * gpr) return;
    int r = idx / gpr;
    int c0 = (idx - r * gpr) * 8;
    __nv_bfloat16 hv[8], lv[8];
#pragma unroll
    for (int i = 0; i < 8; ++i) {
        int c = c0 + i;
        float v = (r < srcR && c < srcC) ? __ldg(&src[(size_t)r * srcC + c]) : 0.f;
        hv[i] = __float2bfloat16(v);
        lv[i] = __float2bfloat16(v - __bfloat162float(hv[i]));
    }
    *(uint4*)&hi[(size_t)r * dstC + c0] = *(uint4*)hv;
    *(uint4*)&lo[(size_t)r * dstC + c0] = *(uint4*)lv;
}

__global__ void conv_all(const float* __restrict__ x,
                         const float* __restrict__ wih,
                         const float* __restrict__ wo)
{
    int gb = blockIdx.x;
    if (gb < NB_X) {
        conv_body(x, g_xhi, g_xlo, MROWS, FF, MROWS, KP1,
                  gb * 256 + threadIdx.x);
    } else if (gb < NB_X + NB_WIH) {
        conv_body(wih, g_wihhi, g_wihlo, G4, FF, NP1, KP1,
                  (gb - NB_X) * 256 + threadIdx.x);
    } else {
        conv_body(wo, g_wohi, g_wolo, FF, HH, NP2, KP2,
                  (gb - NB_X - NB_WIH) * 256 + threadIdx.x);
    }
}

// ===========================================================================
// Pure-bf16 NT GEMM with bias, hi/lo split accumulation (lo*lo dropped).
// Block 128x128, KC=32, cp.async double-buffered. 8 warps 2(m)x4(n).
// nj-granular skip for columns >= Nreal (kills padding MMAs).
// Epilogue: fragments -> swizzled smem -> warp-per-row coalesced stores.
// __launch_bounds__(256,2): regs<=128 -> 2 CTAs/SM.
// ===========================================================================
#define LDR 40
#define MAT_BYTES (128 * LDR * 2)        // 10240
#define STAGE_BYTES (4 * MAT_BYTES)      // 40960
#define SMEM_BIAS (2 * STAGE_BYTES)      // bias at 81920
#define SMEM_TOTAL (SMEM_BIAS + 512)     // 82432

__global__ __launch_bounds__(256, 2) void gemm_bf16_nt(
    const __nv_bfloat16* __restrict__ Ahi, const __nv_bfloat16* __restrict__ Alo,
    const __nv_bfloat16* __restrict__ Bhi, const __nv_bfloat16* __restrict__ Blo,
    const float* __restrict__ bias, float* __restrict__ C,
    int ldc, int Nreal, int Kp, int nKC)
{
    extern __shared__ __align__(16) char smem[];
    const uint32_t sbase = smem_u32(smem);
    float* bias_s = (float*)(smem + SMEM_BIAS);

    const int tid  = threadIdx.x;
    const int lane = tid & 31;
    const int wid  = tid >> 5;
    const int wm   = wid & 1;
    const int wn   = wid >> 1;

    const int m0 = blockIdx.x * 128;
    const int n0 = blockIdx.y * 128;

    // active-column masks (warp-uniform)
    bool nj_act[4], jj_act[2];
#pragma unroll
    for (int nj = 0; nj < 4; ++nj)
        nj_act[nj] = (n0 + wn * 32 + nj * 8) < Nreal;
    jj_act[0] = nj_act[0] | nj_act[1];
    jj_act[1] = nj_act[2] | nj_act[3];
    const bool warp_act = jj_act[0] | jj_act[1];

    float acc[4][4][4];
#pragma unroll
    for (int i = 0; i < 4; ++i)
#pragma unroll
        for (int j = 0; j < 4; ++j)
#pragma unroll
            for (int q = 0; q < 4; ++q) acc[i][j][q] = 0.f;

    auto issue = [&](int kc, int stage) {
        const uint32_t s32 = sbase + stage * STAGE_BYTES;
#pragma unroll
        for (int i = 0; i < 2; ++i) {
            const int chunk = tid + i * 256;      // 0..511
            const int row = chunk >> 2;
            const int g = chunk & 3;
            const uint32_t dofs = row * 80 + g * 16;
            const size_t aofs = (size_t)(m0 + row) * Kp + kc * 32 + g * 8;
            const size_t bofs = (size_t)(n0 + row) * Kp + kc * 32 + g * 8;
            cpasync16(s32 + 0 * MAT_BYTES + dofs, Ahi + aofs);
            cpasync16(s32 + 1 * MAT_BYTES + dofs, Alo + aofs);
            cpasync16(s32 + 2 * MAT_BYTES + dofs, Bhi + bofs);
            cpasync16(s32 + 3 * MAT_BYTES + dofs, Blo + bofs);
        }
    };

    issue(0, 0);
    CP_COMMIT();
    if (tid < 128)
        bias_s[tid] = (n0 + tid < Nreal) ? bias[n0 + tid] : 0.f;

    for (int kc = 0; kc < nKC; ++kc) {
        const int cur = kc & 1;
        CP_WAIT0();
        __syncthreads();

        if (kc + 1 < nKC) {
            issue(kc + 1, cur ^ 1);
            CP_COMMIT();
        }

        const uint32_t sAhi = sbase + cur * STAGE_BYTES;
        const uint32_t sAlo = sAhi + MAT_BYTES;
        const uint32_t sBhi = sAhi + 2 * MAT_BYTES;
        const uint32_t sBlo = sAhi + 3 * MAT_BYTES;

        if (warp_act) {
#pragma unroll
            for (int k16 = 0; k16 < 2; ++k16) {
                const uint32_t kb = k16 * 32;

                uint32_t ah[4][4], al[4][4];
#pragma unroll
                for (int mi = 0; mi < 4; ++mi) {
                    const uint32_t off =
                        (uint32_t)(wm * 64 + mi * 16 + (lane & 15)) * 80 +
                        ((lane >> 4) * 16) + kb;
                    ldsm4(ah[mi], sAhi + off);
                    ldsm4(al[mi], sAlo + off);
                }
                uint32_t bh[4][2], bl[4][2];
#pragma unroll
                for (int jj = 0; jj < 2; ++jj) {
                    if (!jj_act[jj]) continue;
                    const uint32_t nrow =
                        (uint32_t)(wn * 32 + jj * 16 + ((lane >> 4) & 1) * 8 +
                                   (lane & 7));
                    const uint32_t off =
                        nrow * 80 + (((lane >> 3) & 1) * 16) + kb;
                    uint32_t t[4];
                    ldsm4(t, sBhi + off);
                    bh[jj * 2][0] = t[0]; bh[jj * 2][1] = t[1];
                    bh[jj * 2 + 1][0] = t[2]; bh[jj * 2 + 1][1] = t[3];
                    ldsm4(t, sBlo + off);
                    bl[jj * 2][0] = t[0]; bl[jj * 2][1] = t[1];
                    bl[jj * 2 + 1][0] = t[2]; bl[jj * 2 + 1][1] = t[3];
                }
#pragma unroll
                for (int mi = 0; mi < 4; ++mi)
#pragma unroll
                    for (int nj = 0; nj < 4; ++nj) {
                        if (!nj_act[nj]) continue;
                        mma16816(acc[mi][nj], ah[mi], bh[nj]);
                        mma16816(acc[mi][nj], ah[mi], bl[nj]);
                        mma16816(acc[mi][nj], al[mi], bh[nj]);
                    }
            }
        }
    }

    // ---- epilogue: stage into swizzled smem, then coalesced stores
    __syncthreads();
    float* sC = (float*)smem;   // 128x128 fp32 = 64 KB (stages no longer needed)
#pragma unroll
    for (int mi = 0; mi < 4; ++mi) {
        const int rl = wm * 64 + mi * 16 + (lane >> 2);
        const int sw = (rl & 7) << 2;   // same for rl and rl+8
#pragma unroll
        for (int nj = 0; nj < 4; ++nj) {
            const int cl = wn * 32 + nj * 8 + (lane & 3) * 2;
            const int cs = cl ^ sw;
            sC[rl * 128 + cs]           = acc[mi][nj][0];
            sC[rl * 128 + cs + 1]       = acc[mi][nj][1];
            sC[(rl + 8) * 128 + cs]     = acc[mi][nj][2];
            sC[(rl + 8) * 128 + cs + 1] = acc[mi][nj][3];
        }
    }
    __syncthreads();

    // warp w handles rows w, w+8, ..., w+120; lane covers 4 cols (float4)
    const bool al4 = ((ldc & 3) == 0);
#pragma unroll 4
    for (int rr = 0; rr < 16; ++rr) {
        const int row = wid + rr * 8;
        const int col = lane * 4;
        const int swr = (row & 7) << 2;
        float4 v = *(const float4*)&sC[row * 128 + (col ^ swr)];
        float4 bb = *(const float4*)&bias_s[col];
        v.x += bb.x; v.y += bb.y; v.z += bb.z; v.w += bb.w;
        float* dst = C + (size_t)(m0 + row) * ldc + n0 + col;
        if (al4) {
            *(float4*)dst = v;   // padded C (xg): always safe
        } else {
            if (n0 + col + 3 < Nreal) {
                dst[0] = v.x; dst[1] = v.y; dst[2] = v.z; dst[3] = v.w;
            } else {
                if (n0 + col + 0 < Nreal) dst[0] = v.x;
                if (n0 + col + 1 < Nreal) dst[1] = v.y;
                if (n0 + col + 2 < Nreal) dst[2] = v.z;
                if (n0 + col + 3 < Nreal) dst[3] = v.w;
            }
        }
    }
}

// ---------------------------------------------------------------------------
// Column-512 GEMV: out[m, 512] = sum_k hs[m,k] * W_out[512,k] + b_out[512]
// ---------------------------------------------------------------------------
__global__ __launch_bounds__(256) void gemv_col512(
    const float* __restrict__ W_out, const float* __restrict__ b_out,
    float* __restrict__ out)
{
    const int gw = (blockIdx.x * 256 + threadIdx.x) >> 5;
    const int lane = threadIdx.x & 31;
    if (gw >= MROWS) return;

    const uint32_t hw = ((const uint32_t*)(g_hshi + (size_t)gw * KP2))[lane];
    const uint32_t lw = ((const uint32_t*)(g_hslo + (size_t)gw * KP2))[lane];
    __nv_bfloat162 h2 = *(const __nv_bfloat162*)&hw;
    __nv_bfloat162 l2 = *(const __nv_bfloat162*)&lw;
    const int k = lane * 2;
    float h0 = __bfloat162float(h2.x) + __bfloat162float(l2.x);
    float h1 = __bfloat162float(h2.y) + __bfloat162float(l2.y);
    float w0 = (k < HH) ? W_out[512 * HH + k] : 0.f;
    float w1 = (k + 1 < HH) ? W_out[512 * HH + k + 1] : 0.f;
    float s = h0 * w0 + h1 * w1;
#pragma unroll
    for (int o = 16; o > 0; o >>= 1)
        s += __shfl_down_sync(0xFFFFFFFFu, s, o);
    if (lane == 0) out[(size_t)gw * FF + 512] = s + b_out[512];
}

// ---------------------------------------------------------------------------
// LSTM scan over batch axis. One block per t (grid 512, 256 threads).
// xg for step b+1 prefetched during step b. Writes h as bf16 hi/lo.
// ---------------------------------------------------------------------------
__global__ __launch_bounds__(256) void lstm_scan(
    const float* __restrict__ W_hh, const float* __restrict__ b_hh)
{
    __shared__ __align__(16) float h_s[HH + 2];
    __shared__ float g_s[G4];

    const int t = blockIdx.x;
    const int j = threadIdx.x;

    float w[HH];
    float bj = 0.f;
    if (j < G4) {
#pragma unroll
        for (int k = 0; k < HH; ++k) w[k] = W_hh[j * HH + k];
        bj = b_hh[j];
    }
    float c = 0.f;
    if (j < HH + 2) h_s[j] = 0.f;

    float pre = (j < G4) ? g_xg[(size_t)t * XGS + j] : 0.f;   // b=0
    __syncthreads();

    for (int b = 0; b < BB; ++b) {
        if (j < G4) {
            float g0 = pre + bj;
            if (b + 1 < BB)
                pre = g_xg[((size_t)(b + 1) * TT + t) * XGS + j];
            float g1 = 0.f, g2 = 0.f, g3 = 0.f;
#pragma unroll
            for (int k = 0; k < 48; k += 4) {
                float4 hv = *(const float4*)&h_s[k];
                g0 += w[k + 0] * hv.x;
                g1 += w[k + 1] * hv.y;
                g2 += w[k + 2] * hv.z;
                g3 += w[k + 3] * hv.w;
            }
            g0 += w[48] * h_s[48];
            g1 += w[49] * h_s[49];
            g_s[j] = (g0 + g1) + (g2 + g3);
        }
        __syncthreads();
        if (j < KP2) {
            float hv = 0.f;
            if (j < HH) {
                float gi = g_s[j];
                float gf = g_s[j + HH];
                float gg = g_s[j + 2 * HH];
                float go = g_s[j + 3 * HH];
                float si = 1.f / (1.f + expf(-gi));
                float sf = 1.f / (1.f + expf(-gf));
                float so = 1.f / (1.f + expf(-go));
                float tg = tanhf(gg);
                c = sf * c + si * tg;
                hv = so * tanhf(c);
                h_s[j] = hv;
            }
            __nv_bfloat16 hh = __float2bfloat16(hv);
            const size_t o = ((size_t)b * TT + t) * KP2 + j;
            g_hshi[o] = hh;
            g_hslo[o] = __float2bfloat16(hv - __bfloat162float(hh));
        }
        __syncthreads();
    }
}

// ---------------------------------------------------------------------------
extern "C" void kernel_launch(void* const* d_in, const int* in_sizes, int n_in,
                              void* d_out, int out_size)
{
    const float* x     = (const float*)d_in[0];
    const float* W_ih  = (const float*)d_in[1];
    const float* W_hh  = (const float*)d_in[2];
    const float* b_ih  = (const float*)d_in[3];
    const float* b_hh  = (const float*)d_in[4];
    const float* W_out = (const float*)d_in[5];
    const float* b_out = (const float*)d_in[6];
    float* out = (float*)d_out;

    float* xg = nullptr;
    __nv_bfloat16 *xhi, *xlo, *wihhi, *wihlo, *hshi, *hslo, *wohi, *wolo;
    cudaGetSymbolAddress((void**)&xg, g_xg);
    cudaGetSymbolAddress((void**)&xhi, g_xhi);
    cudaGetSymbolAddress((void**)&xlo, g_xlo);
    cudaGetSymbolAddress((void**)&wihhi, g_wihhi);
    cudaGetSymbolAddress((void**)&wihlo, g_wihlo);
    cudaGetSymbolAddress((void**)&hshi, g_hshi);
    cudaGetSymbolAddress((void**)&hslo, g_hslo);
    cudaGetSymbolAddress((void**)&wohi, g_wohi);
    cudaGetSymbolAddress((void**)&wolo, g_wolo);

    cudaFuncSetAttribute(gemm_bf16_nt,
                         cudaFuncAttributeMaxDynamicSharedMemorySize,
                         SMEM_TOTAL);

    // 0) merged conversions (hi/lo bf16, zero-padded)
    conv_all<<<NB_X + NB_WIH + NB_WO, 256>>>(x, W_ih, W_out);

    // 1) xg = x @ W_ih^T + b_ih   (M=32768, Nreal=200, Kp=544, ldc=256)
    {
        dim3 grid(MROWS / 128, NP1 / 128);   // (256, 2)
        gemm_bf16_nt<<<grid, 256, SMEM_TOTAL>>>(xhi, xlo, wihhi, wihlo,
                                                b_ih, xg, XGS, G4, KP1, NKC1);
    }
    // 2) LSTM scan (writes hs as bf16 hi/lo)
    lstm_scan<<<TT, 256>>>(W_hh, b_hh);

    // 3) out[:, 0:512] = hs @ W_out[0:512]^T + b_out  (ldc=513, Nreal=512)
    {
        dim3 grid(MROWS / 128, NP2 / 128);   // (256, 4)
        gemm_bf16_nt<<<grid, 256, SMEM_TOTAL>>>(hshi, hslo, wohi, wolo,
                                                b_out, out, FF, NP2, KP2, NKC2);
    }
    // 3b) out[:, 512] via warp-per-row GEMV
    gemv_col512<<<MROWS / 8, 256>>>(W_out, b_out, out);
}

// round 11
// speedup vs baseline: 1.2652x; 1.0969x over previous
#include <cuda_runtime.h>
#include <cuda_bf16.h>
#include <math.h>
#include <stdint.h>

// Problem constants (fixed by the reference)
#define BB 64
#define TT 512
#define FF 513
#define HH 50
#define G4 200          // 4*H
#define MROWS (BB*TT)   // 32768

#define KP1 544         // K=513 padded to 17*32
#define NKC1 17
#define KP2 64          // K=50 padded to 2*32
#define NKC2 2
#define NP1 256         // W_ih rows padded
#define NP2 512         // W_out rows 0..511 (col 512 via gemv)
#define XGS 256         // xg row stride (padded for aligned float4 stores)

// Scratch (static device globals — no allocation in kernel_launch)
__device__ float g_xg[MROWS * XGS];
__device__ __nv_bfloat16 g_wihhi[NP1 * KP1];
__device__ __nv_bfloat16 g_wihlo[NP1 * KP1];
__device__ __nv_bfloat16 g_hshi[MROWS * KP2];
__device__ __nv_bfloat16 g_hslo[MROWS * KP2];
__device__ __nv_bfloat16 g_wohi[NP2 * KP2];
__device__ __nv_bfloat16 g_wolo[NP2 * KP2];

// ===========================================================================
// PTX helpers
// ===========================================================================
__device__ __forceinline__ uint32_t smem_u32(const void* p) {
    uint32_t a;
    asm("{ .reg .u64 t; cvta.to.shared.u64 t, %1; cvt.u32.u64 %0, t; }"
        : "=r"(a) : "l"(p));
    return a;
}
__device__ __forceinline__ void ldsm4(uint32_t* r, uint32_t a) {
    asm volatile("ldmatrix.sync.aligned.m8n8.x4.shared.b16 {%0,%1,%2,%3}, [%4];"
                 : "=r"(r[0]), "=r"(r[1]), "=r"(r[2]), "=r"(r[3]) : "r"(a));
}
__device__ __forceinline__ void mma16816(float* c, const uint32_t* a,
                                         const uint32_t* b) {
    asm volatile(
        "mma.sync.aligned.m16n8k16.row.col.f32.bf16.bf16.f32 "
        "{%0,%1,%2,%3}, {%4,%5,%6,%7}, {%8,%9}, {%0,%1,%2,%3};"
        : "+f"(c[0]), "+f"(c[1]), "+f"(c[2]), "+f"(c[3])
        : "r"(a[0]), "r"(a[1]), "r"(a[2]), "r"(a[3]), "r"(b[0]), "r"(b[1]));
}
__device__ __forceinline__ void cpasync16(uint32_t dst, const void* src) {
    asm volatile("cp.async.cg.shared.global [%0], [%1], 16;"
                 :: "r"(dst), "l"(src));
}
__device__ __forceinline__ void cpasync4_zfill(uint32_t dst, const void* src,
                                               int srcsz) {
    asm volatile("cp.async.ca.shared.global [%0], [%1], 4, %2;"
                 :: "r"(dst), "l"(src), "r"(srcsz));
}
#define CP_COMMIT() asm volatile("cp.async.commit_group;" ::: "memory")
#define CP_WAIT0()  asm volatile("cp.async.wait_group 0;" ::: "memory")

// ===========================================================================
// Weight conversion: fp32 -> zero-padded bf16 hi/lo (W_ih, W_out only).
// ===========================================================================
#define NB_WIH ((NP1 * (KP1/8) + 255) / 256)        // 68
#define NB_WO  ((NP2 * (KP2/8) + 255) / 256)        // 16

__device__ __forceinline__ void conv_body(
    const float* __restrict__ src, __nv_bfloat16* __restrict__ hi,
    __nv_bfloat16* __restrict__ lo, int srcR, int srcC, int dstR, int dstC,
    int idx)
{
    int gpr = dstC >> 3;
    if (idx >= dstR * gpr) return;
    int r = idx / gpr;
    int c0 = (idx - r * gpr) * 8;
    __nv_bfloat16 hv[8], lv[8];
#pragma unroll
    for (int i = 0; i < 8; ++i) {
        int c = c0 + i;
        float v = (r < srcR && c < srcC) ? __ldg(&src[(size_t)r * srcC + c]) : 0.f;
        hv[i] = __float2bfloat16(v);
        lv[i] = __float2bfloat16(v - __bfloat162float(hv[i]));
    }
    *(uint4*)&hi[(size_t)r * dstC + c0] = *(uint4*)hv;
    *(uint4*)&lo[(size_t)r * dstC + c0] = *(uint4*)lv;
}

__global__ void conv_w(const float* __restrict__ wih,
                       const float* __restrict__ wo)
{
    int gb = blockIdx.x;
    if (gb < NB_WIH)
        conv_body(wih, g_wihhi, g_wihlo, G4, FF, NP1, KP1,
                  gb * 256 + threadIdx.x);
    else
        conv_body(wo, g_wohi, g_wolo, FF, HH, NP2, KP2,
                  (gb - NB_WIH) * 256 + threadIdx.x);
}

// ===========================================================================
// Shared GEMM building blocks
// ===========================================================================
#define LDR80 80
#define ABF_BYTES 10240                  // 128 rows x 80 B (bf16 tile)

// ---------------------------------------------------------------------------
// FUSED GEMM1: xg[m, 0:200] = x[m,:] @ W_ih^T + b_ih, fp32 x converted
// to bf16 hi/lo IN-KERNEL (smem staging). Block 128x128, KC=32.
// Grid (2, 256): n-tile fastest -> A re-read hits L2.
// ---------------------------------------------------------------------------
#define RAW_OFF   0
#define RAW_ROWB  144                    // 32 fp32 (128 B) + 16 B pad
#define RAW_BYTES (128 * RAW_ROWB)       // 18432
#define CONVA_OFF RAW_BYTES              // 18432
#define CONVA_ST  (2 * ABF_BYTES)        // 20480 per stage (hi|lo)
#define B1_OFF    (CONVA_OFF + 2 * CONVA_ST)   // 59392
#define B1_ST     (2 * ABF_BYTES)
#define BIAS1_OFF (B1_OFF + 2 * B1_ST)   // 100352
#define SMEM1_TOTAL (BIAS1_OFF + 512)    // 100864

__global__ __launch_bounds__(256, 2) void gemm1_fused(
    const float* __restrict__ x,
    const __nv_bfloat16* __restrict__ Bhi, const __nv_bfloat16* __restrict__ Blo,
    const float* __restrict__ bias, float* __restrict__ C)
{
    extern __shared__ __align__(16) char smem[];
    const uint32_t sbase = smem_u32(smem);
    float* bias_s = (float*)(smem + BIAS1_OFF);

    const int tid  = threadIdx.x;
    const int lane = tid & 31;
    const int wid  = tid >> 5;
    const int wm   = wid & 1;
    const int wn   = wid >> 1;

    const int n0 = blockIdx.x * 128;   // n fastest
    const int m0 = blockIdx.y * 128;

    bool nj_act[4], jj_act[2];
#pragma unroll
    for (int nj = 0; nj < 4; ++nj)
        nj_act[nj] = (n0 + wn * 32 + nj * 8) < G4;
    jj_act[0] = nj_act[0] | nj_act[1];
    jj_act[1] = nj_act[2] | nj_act[3];
    const bool warp_act = jj_act[0] | jj_act[1];

    float acc[4][4][4];
#pragma unroll
    for (int i = 0; i < 4; ++i)
#pragma unroll
        for (int j = 0; j < 4; ++j)
#pragma unroll
            for (int q = 0; q < 4; ++q) acc[i][j][q] = 0.f;

    // raw fp32 A chunk: 128 x 32 fp32, 4-byte zfill cp.async (row stride 513)
    auto issueA = [&](int kc) {
#pragma unroll
        for (int i = 0; i < 16; ++i) {
            const int w = tid + i * 256;       // 0..4095
            const int row = w >> 5;
            const int col = w & 31;
            const int gc = kc * 32 + col;
            const uint32_t dst = sbase + RAW_OFF + row * RAW_ROWB + col * 4;
            const float* src = x + (size_t)(m0 + row) * FF + gc;
            cpasync4_zfill(dst, src, (gc < FF) ? 4 : 0);
        }
    };
    // B chunk (pre-converted bf16 hi/lo, Kp1 stride)
    auto issueB = [&](int kc, int stage) {
        const uint32_t s32 = sbase + B1_OFF + stage * B1_ST;
#pragma unroll
        for (int i = 0; i < 2; ++i) {
            const int chunk = tid + i * 256;   // 0..511
            const int row = chunk >> 2;
            const int g = chunk & 3;
            const uint32_t dofs = row * LDR80 + g * 16;
            const size_t bofs = (size_t)(n0 + row) * KP1 + kc * 32 + g * 8;
            cpasync16(s32 + dofs, Bhi + bofs);
            cpasync16(s32 + ABF_BYTES + dofs, Blo + bofs);
        }
    };

    issueA(0);
    issueB(0, 0);
    CP_COMMIT();
    if (tid < 128)
        bias_s[tid] = (n0 + tid < G4) ? bias[n0 + tid] : 0.f;

    const int crow  = tid >> 1;
    const int chalf = (tid & 1) << 4;   // 0 or 16

    for (int kc = 0; kc < NKC1; ++kc) {
        const int cur = kc & 1;
        CP_WAIT0();
        __syncthreads();   // raw A kc + B kc ready; prior compute done

        // ---- convert raw fp32 -> bf16 hi/lo into conv stage `cur`
        {
            const float4* rp =
                (const float4*)(smem + RAW_OFF + crow * RAW_ROWB + chalf * 4);
            float f[16];
#pragma unroll
            for (int i = 0; i < 4; ++i)
                *(float4*)&f[i * 4] = rp[i];
            __nv_bfloat16 hv[16], lv[16];
#pragma unroll
            for (int i = 0; i < 16; ++i) {
                hv[i] = __float2bfloat16(f[i]);
                lv[i] = __float2bfloat16(f[i] - __bfloat162float(hv[i]));
            }
            char* hd = smem + CONVA_OFF + cur * CONVA_ST + crow * LDR80 + chalf * 2;
            *(uint4*)hd        = ((uint4*)hv)[0];
            *(uint4*)(hd + 16) = ((uint4*)hv)[1];
            char* ld2 = hd + ABF_BYTES;
            *(uint4*)ld2        = ((uint4*)lv)[0];
            *(uint4*)(ld2 + 16) = ((uint4*)lv)[1];
        }
        __syncthreads();   // conversions visible; raw buffer free

        if (kc + 1 < NKC1) {
            issueA(kc + 1);
            issueB(kc + 1, cur ^ 1);
            CP_COMMIT();
        }

        const uint32_t sAhi = sbase + CONVA_OFF + cur * CONVA_ST;
        const uint32_t sAlo = sAhi + ABF_BYTES;
        const uint32_t sBhi = sbase + B1_OFF + cur * B1_ST;
        const uint32_t sBlo = sBhi + ABF_BYTES;

        if (warp_act) {
#pragma unroll
            for (int k16 = 0; k16 < 2; ++k16) {
                const uint32_t kb = k16 * 32;
                uint32_t ah[4][4], al[4][4];
#pragma unroll
                for (int mi = 0; mi < 4; ++mi) {
                    const uint32_t off =
                        (uint32_t)(wm * 64 + mi * 16 + (lane & 15)) * LDR80 +
                        ((lane >> 4) * 16) + kb;
                    ldsm4(ah[mi], sAhi + off);
                    ldsm4(al[mi], sAlo + off);
                }
                uint32_t bh[4][2], bl[4][2];
#pragma unroll
                for (int jj = 0; jj < 2; ++jj) {
                    if (!jj_act[jj]) continue;
                    const uint32_t nrow =
                        (uint32_t)(wn * 32 + jj * 16 + ((lane >> 4) & 1) * 8 +
                                   (lane & 7));
                    const uint32_t off =
                        nrow * LDR80 + (((lane >> 3) & 1) * 16) + kb;
                    uint32_t t[4];
                    ldsm4(t, sBhi + off);
                    bh[jj * 2][0] = t[0]; bh[jj * 2][1] = t[1];
                    bh[jj * 2 + 1][0] = t[2]; bh[jj * 2 + 1][1] = t[3];
                    ldsm4(t, sBlo + off);
                    bl[jj * 2][0] = t[0]; bl[jj * 2][1] = t[1];
                    bl[jj * 2 + 1][0] = t[2]; bl[jj * 2 + 1][1] = t[3];
                }
#pragma unroll
                for (int mi = 0; mi < 4; ++mi)
#pragma unroll
                    for (int nj = 0; nj < 4; ++nj) {
                        if (!nj_act[nj]) continue;
                        mma16816(acc[mi][nj], ah[mi], bh[nj]);
                        mma16816(acc[mi][nj], ah[mi], bl[nj]);
                        mma16816(acc[mi][nj], al[mi], bh[nj]);
                    }
            }
        }
    }

    // ---- epilogue via swizzled smem (reuses stage area), coalesced stores
    __syncthreads();
    float* sC = (float*)smem;   // 64 KB < BIAS1_OFF, bias safe
#pragma unroll
    for (int mi = 0; mi < 4; ++mi) {
        const int rl = wm * 64 + mi * 16 + (lane >> 2);
        const int sw = (rl & 7) << 2;
#pragma unroll
        for (int nj = 0; nj < 4; ++nj) {
            const int cl = wn * 32 + nj * 8 + (lane & 3) * 2;
            const int cs = cl ^ sw;
            sC[rl * 128 + cs]           = acc[mi][nj][0];
            sC[rl * 128 + cs + 1]       = acc[mi][nj][1];
            sC[(rl + 8) * 128 + cs]     = acc[mi][nj][2];
            sC[(rl + 8) * 128 + cs + 1] = acc[mi][nj][3];
        }
    }
    __syncthreads();
#pragma unroll 4
    for (int rr = 0; rr < 16; ++rr) {
        const int row = wid + rr * 8;
        const int col = lane * 4;
        const int swr = (row & 7) << 2;
        float4 v = *(const float4*)&sC[row * 128 + (col ^ swr)];
        float4 bb = *(const float4*)&bias_s[col];
        v.x += bb.x; v.y += bb.y; v.z += bb.z; v.w += bb.w;
        *(float4*)(C + (size_t)(m0 + row) * XGS + n0 + col) = v;
    }
}

// ---------------------------------------------------------------------------
// Generic pre-converted bf16 GEMM (GEMM2). R10 design.
// ---------------------------------------------------------------------------
#define MAT_BYTES ABF_BYTES
#define STAGE_BYTES (4 * MAT_BYTES)      // 40960
#define SMEM_BIAS (2 * STAGE_BYTES)
#define SMEM_TOTAL (SMEM_BIAS + 512)     // 82432

__global__ __launch_bounds__(256, 2) void gemm_bf16_nt(
    const __nv_bfloat16* __restrict__ Ahi, const __nv_bfloat16* __restrict__ Alo,
    const __nv_bfloat16* __restrict__ Bhi, const __nv_bfloat16* __restrict__ Blo,
    const float* __restrict__ bias, float* __restrict__ C,
    int ldc, int Nreal, int Kp, int nKC)
{
    extern __shared__ __align__(16) char smem[];
    const uint32_t sbase = smem_u32(smem);
    float* bias_s = (float*)(smem + SMEM_BIAS);

    const int tid  = threadIdx.x;
    const int lane = tid & 31;
    const int wid  = tid >> 5;
    const int wm   = wid & 1;
    const int wn   = wid >> 1;

    const int m0 = blockIdx.x * 128;
    const int n0 = blockIdx.y * 128;

    bool nj_act[4], jj_act[2];
#pragma unroll
    for (int nj = 0; nj < 4; ++nj)
        nj_act[nj] = (n0 + wn * 32 + nj * 8) < Nreal;
    jj_act[0] = nj_act[0] | nj_act[1];
    jj_act[1] = nj_act[2] | nj_act[3];
    const bool warp_act = jj_act[0] | jj_act[1];

    float acc[4][4][4];
#pragma unroll
    for (int i = 0; i < 4; ++i)
#pragma unroll
        for (int j = 0; j < 4; ++j)
#pragma unroll
            for (int q = 0; q < 4; ++q) acc[i][j][q] = 0.f;

    auto issue = [&](int kc, int stage) {
        const uint32_t s32 = sbase + stage * STAGE_BYTES;
#pragma unroll
        for (int i = 0; i < 2; ++i) {
            const int chunk = tid + i * 256;
            const int row = chunk >> 2;
            const int g = chunk & 3;
            const uint32_t dofs = row * LDR80 + g * 16;
            const size_t aofs = (size_t)(m0 + row) * Kp + kc * 32 + g * 8;
            const size_t bofs = (size_t)(n0 + row) * Kp + kc * 32 + g * 8;
            cpasync16(s32 + 0 * MAT_BYTES + dofs, Ahi + aofs);
            cpasync16(s32 + 1 * MAT_BYTES + dofs, Alo + aofs);
            cpasync16(s32 + 2 * MAT_BYTES + dofs, Bhi + bofs);
            cpasync16(s32 + 3 * MAT_BYTES + dofs, Blo + bofs);
        }
    };

    issue(0, 0);
    CP_COMMIT();
    if (tid < 128)
        bias_s[tid] = (n0 + tid < Nreal) ? bias[n0 + tid] : 0.f;

    for (int kc = 0; kc < nKC; ++kc) {
        const int cur = kc & 1;
        CP_WAIT0();
        __syncthreads();

        if (kc + 1 < nKC) {
            issue(kc + 1, cur ^ 1);
            CP_COMMIT();
        }

        const uint32_t sAhi = sbase + cur * STAGE_BYTES;
        const uint32_t sAlo = sAhi + MAT_BYTES;
        const uint32_t sBhi = sAhi + 2 * MAT_BYTES;
        const uint32_t sBlo = sAhi + 3 * MAT_BYTES;

        if (warp_act) {
#pragma unroll
            for (int k16 = 0; k16 < 2; ++k16) {
                const uint32_t kb = k16 * 32;
                uint32_t ah[4][4], al[4][4];
#pragma unroll
                for (int mi = 0; mi < 4; ++mi) {
                    const uint32_t off =
                        (uint32_t)(wm * 64 + mi * 16 + (lane & 15)) * LDR80 +
                        ((lane >> 4) * 16) + kb;
                    ldsm4(ah[mi], sAhi + off);
                    ldsm4(al[mi], sAlo + off);
                }
                uint32_t bh[4][2], bl[4][2];
#pragma unroll
                for (int jj = 0; jj < 2; ++jj) {
                    if (!jj_act[jj]) continue;
                    const uint32_t nrow =
                        (uint32_t)(wn * 32 + jj * 16 + ((lane >> 4) & 1) * 8 +
                                   (lane & 7));
                    const uint32_t off =
                        nrow * LDR80 + (((lane >> 3) & 1) * 16) + kb;
                    uint32_t t[4];
                    ldsm4(t, sBhi + off);
                    bh[jj * 2][0] = t[0]; bh[jj * 2][1] = t[1];
                    bh[jj * 2 + 1][0] = t[2]; bh[jj * 2 + 1][1] = t[3];
                    ldsm4(t, sBlo + off);
                    bl[jj * 2][0] = t[0]; bl[jj * 2][1] = t[1];
                    bl[jj * 2 + 1][0] = t[2]; bl[jj * 2 + 1][1] = t[3];
                }
#pragma unroll
                for (int mi = 0; mi < 4; ++mi)
#pragma unroll
                    for (int nj = 0; nj < 4; ++nj) {
                        if (!nj_act[nj]) continue;
                        mma16816(acc[mi][nj], ah[mi], bh[nj]);
                        mma16816(acc[mi][nj], ah[mi], bl[nj]);
                        mma16816(acc[mi][nj], al[mi], bh[nj]);
                    }
            }
        }
    }

    __syncthreads();
    float* sC = (float*)smem;
#pragma unroll
    for (int mi = 0; mi < 4; ++mi) {
        const int rl = wm * 64 + mi * 16 + (lane >> 2);
        const int sw = (rl & 7) << 2;
#pragma unroll
        for (int nj = 0; nj < 4; ++nj) {
            const int cl = wn * 32 + nj * 8 + (lane & 3) * 2;
            const int cs = cl ^ sw;
            sC[rl * 128 + cs]           = acc[mi][nj][0];
            sC[rl * 128 + cs + 1]       = acc[mi][nj][1];
            sC[(rl + 8) * 128 + cs]     = acc[mi][nj][2];
            sC[(rl + 8) * 128 + cs + 1] = acc[mi][nj][3];
        }
    }
    __syncthreads();

    const bool al4 = ((ldc & 3) == 0);
#pragma unroll 4
    for (int rr = 0; rr < 16; ++rr) {
        const int row = wid + rr * 8;
        const int col = lane * 4;
        const int swr = (row & 7) << 2;
        float4 v = *(const float4*)&sC[row * 128 + (col ^ swr)];
        float4 bb = *(const float4*)&bias_s[col];
        v.x += bb.x; v.y += bb.y; v.z += bb.z; v.w += bb.w;
        float* dst = C + (size_t)(m0 + row) * ldc + n0 + col;
        if (al4) {
            *(float4*)dst = v;
        } else {
            if (n0 + col + 3 < Nreal) {
                dst[0] = v.x; dst[1] = v.y; dst[2] = v.z; dst[3] = v.w;
            } else {
                if (n0 + col + 0 < Nreal) dst[0] = v.x;
                if (n0 + col + 1 < Nreal) dst[1] = v.y;
                if (n0 + col + 2 < Nreal) dst[2] = v.z;
                if (n0 + col + 3 < Nreal) dst[3] = v.w;
            }
        }
    }
}

// ---------------------------------------------------------------------------
// Column-512 GEMV: out[m, 512] = sum_k hs[m,k] * W_out[512,k] + b_out[512]
// ---------------------------------------------------------------------------
__global__ __launch_bounds__(256) void gemv_col512(
    const float* __restrict__ W_out, const float* __restrict__ b_out,
    float* __restrict__ out)
{
    const int gw = (blockIdx.x * 256 + threadIdx.x) >> 5;
    const int lane = threadIdx.x & 31;
    if (gw >= MROWS) return;

    const uint32_t hw = ((const uint32_t*)(g_hshi + (size_t)gw * KP2))[lane];
    const uint32_t lw = ((const uint32_t*)(g_hslo + (size_t)gw * KP2))[lane];
    __nv_bfloat162 h2 = *(const __nv_bfloat162*)&hw;
    __nv_bfloat162 l2 = *(const __nv_bfloat162*)&lw;
    const int k = lane * 2;
    float h0 = __bfloat162float(h2.x) + __bfloat162float(l2.x);
    float h1 = __bfloat162float(h2.y) + __bfloat162float(l2.y);
    float w0 = (k < HH) ? W_out[512 * HH + k] : 0.f;
    float w1 = (k + 1 < HH) ? W_out[512 * HH + k + 1] : 0.f;
    float s = h0 * w0 + h1 * w1;
#pragma unroll
    for (int o = 16; o > 0; o >>= 1)
        s += __shfl_down_sync(0xFFFFFFFFu, s, o);
    if (lane == 0) out[(size_t)gw * FF + 512] = s + b_out[512];
}

// ---------------------------------------------------------------------------
// LSTM scan over batch axis. One block per t (grid 512, 256 threads).
// ---------------------------------------------------------------------------
__global__ __launch_bounds__(256) void lstm_scan(
    const float* __restrict__ W_hh, const float* __restrict__ b_hh)
{
    __shared__ __align__(16) float h_s[HH + 2];
    __shared__ float g_s[G4];

    const int t = blockIdx.x;
    const int j = threadIdx.x;

    float w[HH];
    float bj = 0.f;
    if (j < G4) {
#pragma unroll
        for (int k = 0; k < HH; ++k) w[k] = W_hh[j * HH + k];
        bj = b_hh[j];
    }
    float c = 0.f;
    if (j < HH + 2) h_s[j] = 0.f;

    float pre = (j < G4) ? g_xg[(size_t)t * XGS + j] : 0.f;
    __syncthreads();

    for (int b = 0; b < BB; ++b) {
        if (j < G4) {
            float g0 = pre + bj;
            if (b + 1 < BB)
                pre = g_xg[((size_t)(b + 1) * TT + t) * XGS + j];
            float g1 = 0.f, g2 = 0.f, g3 = 0.f;
#pragma unroll
            for (int k = 0; k < 48; k += 4) {
                float4 hv = *(const float4*)&h_s[k];
                g0 += w[k + 0] * hv.x;
                g1 += w[k + 1] * hv.y;
                g2 += w[k + 2] * hv.z;
                g3 += w[k + 3] * hv.w;
            }
            g0 += w[48] * h_s[48];
            g1 += w[49] * h_s[49];
            g_s[j] = (g0 + g1) + (g2 + g3);
        }
        __syncthreads();
        if (j < KP2) {
            float hv = 0.f;
            if (j < HH) {
                float gi = g_s[j];
                float gf = g_s[j + HH];
                float gg = g_s[j + 2 * HH];
                float go = g_s[j + 3 * HH];
                float si = 1.f / (1.f + expf(-gi));
                float sf = 1.f / (1.f + expf(-gf));
                float so = 1.f / (1.f + expf(-go));
                float tg = tanhf(gg);
                c = sf * c + si * tg;
                hv = so * tanhf(c);
                h_s[j] = hv;
            }
            __nv_bfloat16 hh = __float2bfloat16(hv);
            const size_t o = ((size_t)b * TT + t) * KP2 + j;
            g_hshi[o] = hh;
            g_hslo[o] = __float2bfloat16(hv - __bfloat162float(hh));
        }
        __syncthreads();
    }
}

// ---------------------------------------------------------------------------
extern "C" void kernel_launch(void* const* d_in, const int* in_sizes, int n_in,
                              void* d_out, int out_size)
{
    const float* x     = (const float*)d_in[0];
    const float* W_ih  = (const float*)d_in[1];
    const float* W_hh  = (const float*)d_in[2];
    const float* b_ih  = (const float*)d_in[3];
    const float* b_hh  = (const float*)d_in[4];
    const float* W_out = (const float*)d_in[5];
    const float* b_out = (const float*)d_in[6];
    float* out = (float*)d_out;

    float* xg = nullptr;
    __nv_bfloat16 *wihhi, *wihlo, *hshi, *hslo, *wohi, *wolo;
    cudaGetSymbolAddress((void**)&xg, g_xg);
    cudaGetSymbolAddress((void**)&wihhi, g_wihhi);
    cudaGetSymbolAddress((void**)&wihlo, g_wihlo);
    cudaGetSymbolAddress((void**)&hshi, g_hshi);
    cudaGetSymbolAddress((void**)&hslo, g_hslo);
    cudaGetSymbolAddress((void**)&wohi, g_wohi);
    cudaGetSymbolAddress((void**)&wolo, g_wolo);

    cudaFuncSetAttribute(gemm1_fused,
                         cudaFuncAttributeMaxDynamicSharedMemorySize,
                         SMEM1_TOTAL);
    cudaFuncSetAttribute(gemm_bf16_nt,
                         cudaFuncAttributeMaxDynamicSharedMemorySize,
                         SMEM_TOTAL);

    // 0) weight conversions only (tiny)
    conv_w<<<NB_WIH + NB_WO, 256>>>(W_ih, W_out);

    // 1) xg = x @ W_ih^T + b_ih — fused fp32->bf16 conversion in-kernel
    {
        dim3 grid(NP1 / 128, MROWS / 128);   // (2, 256) n-fastest
        gemm1_fused<<<grid, 256, SMEM1_TOTAL>>>(x, wihhi, wihlo, b_ih, xg);
    }
    // 2) LSTM scan (writes hs as bf16 hi/lo)
    lstm_scan<<<TT, 256>>>(W_hh, b_hh);

    // 3) out[:, 0:512] = hs @ W_out[0:512]^T + b_out
    {
        dim3 grid(MROWS / 128, NP2 / 128);   // (256, 4)
        gemm_bf16_nt<<<grid, 256, SMEM_TOTAL>>>(hshi, hslo, wohi, wolo,
                                                b_out, out, FF, NP2, KP2, NKC2);
    }
    // 3b) out[:, 512] via warp-per-row GEMV
    gemv_col512<<<MROWS / 8, 256>>>(W_out, b_out, out);
}

// round 12
// speedup vs baseline: 1.4162x; 1.1193x over previous
#include <cuda_runtime.h>
#include <cuda_bf16.h>
#include <math.h>
#include <stdint.h>

// Problem constants (fixed by the reference)
#define BB 64
#define TT 512
#define FF 513
#define HH 50
#define G4 200          // 4*H
#define MROWS (BB*TT)   // 32768

#define KP1 544         // K=513 padded to 17*32
#define NKC1 17
#define KP2 64          // K=50 padded to 2*32
#define NKC2 2
#define NP1 256         // W_ih rows padded
#define NP2 512         // W_out rows 0..511 (col 512 via gemv)
#define XGS 256         // xg row stride (padded for aligned float4 stores)

// Scratch (static device globals — no allocation in kernel_launch)
__device__ float g_xg[MROWS * XGS];
__device__ __nv_bfloat16 g_wihhi[NP1 * KP1];
__device__ __nv_bfloat16 g_wihlo[NP1 * KP1];
__device__ __nv_bfloat16 g_hshi[MROWS * KP2];
__device__ __nv_bfloat16 g_hslo[MROWS * KP2];
__device__ __nv_bfloat16 g_wohi[NP2 * KP2];
__device__ __nv_bfloat16 g_wolo[NP2 * KP2];

// ===========================================================================
// PTX helpers
// ===========================================================================
__device__ __forceinline__ uint32_t smem_u32(const void* p) {
    uint32_t a;
    asm("{ .reg .u64 t; cvta.to.shared.u64 t, %1; cvt.u32.u64 %0, t; }"
        : "=r"(a) : "l"(p));
    return a;
}
__device__ __forceinline__ void ldsm4(uint32_t* r, uint32_t a) {
    asm volatile("ldmatrix.sync.aligned.m8n8.x4.shared.b16 {%0,%1,%2,%3}, [%4];"
                 : "=r"(r[0]), "=r"(r[1]), "=r"(r[2]), "=r"(r[3]) : "r"(a));
}
__device__ __forceinline__ void mma16816(float* c, const uint32_t* a,
                                         const uint32_t* b) {
    asm volatile(
        "mma.sync.aligned.m16n8k16.row.col.f32.bf16.bf16.f32 "
        "{%0,%1,%2,%3}, {%4,%5,%6,%7}, {%8,%9}, {%0,%1,%2,%3};"
        : "+f"(c[0]), "+f"(c[1]), "+f"(c[2]), "+f"(c[3])
        : "r"(a[0]), "r"(a[1]), "r"(a[2]), "r"(a[3]), "r"(b[0]), "r"(b[1]));
}
__device__ __forceinline__ void cpasync16(uint32_t dst, const void* src) {
    asm volatile("cp.async.cg.shared.global [%0], [%1], 16;"
                 :: "r"(dst), "l"(src));
}
__device__ __forceinline__ void cpasync4_zfill(uint32_t dst, const void* src,
                                               int srcsz) {
    asm volatile("cp.async.ca.shared.global [%0], [%1], 4, %2;"
                 :: "r"(dst), "l"(src), "r"(srcsz));
}
#define CP_COMMIT() asm volatile("cp.async.commit_group;" ::: "memory")
#define CP_WAIT0()  asm volatile("cp.async.wait_group 0;" ::: "memory")

// fast activations: single MUFU.EX2-based, clamped; rel err ~1e-6
__device__ __forceinline__ float sigm_fast(float x) {
    x = fminf(fmaxf(x, -30.f), 30.f);
    return __fdividef(1.f, 1.f + __expf(-x));
}
__device__ __forceinline__ float tanh_fast(float x) {
    x = fminf(fmaxf(x, -15.f), 15.f);
    float e = __expf(-2.f * x);
    return __fdividef(1.f - e, 1.f + e);
}

// ===========================================================================
// Weight conversion: fp32 -> zero-padded bf16 hi/lo (W_ih, W_out only).
// ===========================================================================
#define NB_WIH ((NP1 * (KP1/8) + 255) / 256)        // 68
#define NB_WO  ((NP2 * (KP2/8) + 255) / 256)        // 16

__device__ __forceinline__ void conv_body(
    const float* __restrict__ src, __nv_bfloat16* __restrict__ hi,
    __nv_bfloat16* __restrict__ lo, int srcR, int srcC, int dstR, int dstC,
    int idx)
{
    int gpr = dstC >> 3;
    if (idx >= dstR * gpr) return;
    int r = idx / gpr;
    int c0 = (idx - r * gpr) * 8;
    __nv_bfloat16 hv[8], lv[8];
#pragma unroll
    for (int i = 0; i < 8; ++i) {
        int c = c0 + i;
        float v = (r < srcR && c < srcC) ? __ldg(&src[(size_t)r * srcC + c]) : 0.f;
        hv[i] = __float2bfloat16(v);
        lv[i] = __float2bfloat16(v - __bfloat162float(hv[i]));
    }
    *(uint4*)&hi[(size_t)r * dstC + c0] = *(uint4*)hv;
    *(uint4*)&lo[(size_t)r * dstC + c0] = *(uint4*)lv;
}

__global__ void conv_w(const float* __restrict__ wih,
                       const float* __restrict__ wo)
{
    int gb = blockIdx.x;
    if (gb < NB_WIH)
        conv_body(wih, g_wihhi, g_wihlo, G4, FF, NP1, KP1,
                  gb * 256 + threadIdx.x);
    else
        conv_body(wo, g_wohi, g_wolo, FF, HH, NP2, KP2,
                  (gb - NB_WIH) * 256 + threadIdx.x);
}

// ===========================================================================
// Shared GEMM building blocks
// ===========================================================================
#define LDR80 80
#define ABF_BYTES 10240                  // 128 rows x 80 B (bf16 tile)

// ---------------------------------------------------------------------------
// FUSED GEMM1: xg[m, 0:200] = x[m,:] @ W_ih^T + b_ih, fp32 x converted
// to bf16 hi/lo IN-KERNEL (smem staging). Block 128x128, KC=32.
// Grid (2, 256): n-tile fastest -> A re-read hits L2.
// ---------------------------------------------------------------------------
#define RAW_OFF   0
#define RAW_ROWB  144                    // 32 fp32 (128 B) + 16 B pad
#define RAW_BYTES (128 * RAW_ROWB)       // 18432
#define CONVA_OFF RAW_BYTES              // 18432
#define CONVA_ST  (2 * ABF_BYTES)        // 20480 per stage (hi|lo)
#define B1_OFF    (CONVA_OFF + 2 * CONVA_ST)   // 59392
#define B1_ST     (2 * ABF_BYTES)
#define BIAS1_OFF (B1_OFF + 2 * B1_ST)   // 100352
#define SMEM1_TOTAL (BIAS1_OFF + 512)    // 100864

__global__ __launch_bounds__(256, 2) void gemm1_fused(
    const float* __restrict__ x,
    const __nv_bfloat16* __restrict__ Bhi, const __nv_bfloat16* __restrict__ Blo,
    const float* __restrict__ bias, float* __restrict__ C)
{
    extern __shared__ __align__(16) char smem[];
    const uint32_t sbase = smem_u32(smem);
    float* bias_s = (float*)(smem + BIAS1_OFF);

    const int tid  = threadIdx.x;
    const int lane = tid & 31;
    const int wid  = tid >> 5;
    const int wm   = wid & 1;
    const int wn   = wid >> 1;

    const int n0 = blockIdx.x * 128;   // n fastest
    const int m0 = blockIdx.y * 128;

    bool nj_act[4], jj_act[2];
#pragma unroll
    for (int nj = 0; nj < 4; ++nj)
        nj_act[nj] = (n0 + wn * 32 + nj * 8) < G4;
    jj_act[0] = nj_act[0] | nj_act[1];
    jj_act[1] = nj_act[2] | nj_act[3];
    const bool warp_act = jj_act[0] | jj_act[1];

    float acc[4][4][4];
#pragma unroll
    for (int i = 0; i < 4; ++i)
#pragma unroll
        for (int j = 0; j < 4; ++j)
#pragma unroll
            for (int q = 0; q < 4; ++q) acc[i][j][q] = 0.f;

    // raw fp32 A chunk: 128 x 32 fp32, 4-byte zfill cp.async (row stride 513)
    auto issueA = [&](int kc) {
#pragma unroll
        for (int i = 0; i < 16; ++i) {
            const int w = tid + i * 256;       // 0..4095
            const int row = w >> 5;
            const int col = w & 31;
            const int gc = kc * 32 + col;
            const uint32_t dst = sbase + RAW_OFF + row * RAW_ROWB + col * 4;
            const float* src = x + (size_t)(m0 + row) * FF + gc;
            cpasync4_zfill(dst, src, (gc < FF) ? 4 : 0);
        }
    };
    // B chunk (pre-converted bf16 hi/lo, Kp1 stride)
    auto issueB = [&](int kc, int stage) {
        const uint32_t s32 = sbase + B1_OFF + stage * B1_ST;
#pragma unroll
        for (int i = 0; i < 2; ++i) {
            const int chunk = tid + i * 256;   // 0..511
            const int row = chunk >> 2;
            const int g = chunk & 3;
            const uint32_t dofs = row * LDR80 + g * 16;
            const size_t bofs = (size_t)(n0 + row) * KP1 + kc * 32 + g * 8;
            cpasync16(s32 + dofs, Bhi + bofs);
            cpasync16(s32 + ABF_BYTES + dofs, Blo + bofs);
        }
    };

    issueA(0);
    issueB(0, 0);
    CP_COMMIT();
    if (tid < 128)
        bias_s[tid] = (n0 + tid < G4) ? bias[n0 + tid] : 0.f;

    const int crow  = tid >> 1;
    const int chalf = (tid & 1) << 4;   // 0 or 16

    for (int kc = 0; kc < NKC1; ++kc) {
        const int cur = kc & 1;
        CP_WAIT0();
        __syncthreads();   // raw A kc + B kc ready; prior compute done

        // ---- convert raw fp32 -> bf16 hi/lo into conv stage `cur`
        {
            const float4* rp =
                (const float4*)(smem + RAW_OFF + crow * RAW_ROWB + chalf * 4);
            float f[16];
#pragma unroll
            for (int i = 0; i < 4; ++i)
                *(float4*)&f[i * 4] = rp[i];
            __nv_bfloat16 hv[16], lv[16];
#pragma unroll
            for (int i = 0; i < 16; ++i) {
                hv[i] = __float2bfloat16(f[i]);
                lv[i] = __float2bfloat16(f[i] - __bfloat162float(hv[i]));
            }
            char* hd = smem + CONVA_OFF + cur * CONVA_ST + crow * LDR80 + chalf * 2;
            *(uint4*)hd        = ((uint4*)hv)[0];
            *(uint4*)(hd + 16) = ((uint4*)hv)[1];
            char* ld2 = hd + ABF_BYTES;
            *(uint4*)ld2        = ((uint4*)lv)[0];
            *(uint4*)(ld2 + 16) = ((uint4*)lv)[1];
        }
        __syncthreads();   // conversions visible; raw buffer free

        if (kc + 1 < NKC1) {
            issueA(kc + 1);
            issueB(kc + 1, cur ^ 1);
            CP_COMMIT();
        }

        const uint32_t sAhi = sbase + CONVA_OFF + cur * CONVA_ST;
        const uint32_t sAlo = sAhi + ABF_BYTES;
        const uint32_t sBhi = sbase + B1_OFF + cur * B1_ST;
        const uint32_t sBlo = sBhi + ABF_BYTES;

        if (warp_act) {
#pragma unroll
            for (int k16 = 0; k16 < 2; ++k16) {
                const uint32_t kb = k16 * 32;
                uint32_t ah[4][4], al[4][4];
#pragma unroll
                for (int mi = 0; mi < 4; ++mi) {
                    const uint32_t off =
                        (uint32_t)(wm * 64 + mi * 16 + (lane & 15)) * LDR80 +
                        ((lane >> 4) * 16) + kb;
                    ldsm4(ah[mi], sAhi + off);
                    ldsm4(al[mi], sAlo + off);
                }
                uint32_t bh[4][2], bl[4][2];
#pragma unroll
                for (int jj = 0; jj < 2; ++jj) {
                    if (!jj_act[jj]) continue;
                    const uint32_t nrow =
                        (uint32_t)(wn * 32 + jj * 16 + ((lane >> 4) & 1) * 8 +
                                   (lane & 7));
                    const uint32_t off =
                        nrow * LDR80 + (((lane >> 3) & 1) * 16) + kb;
                    uint32_t t[4];
                    ldsm4(t, sBhi + off);
                    bh[jj * 2][0] = t[0]; bh[jj * 2][1] = t[1];
                    bh[jj * 2 + 1][0] = t[2]; bh[jj * 2 + 1][1] = t[3];
                    ldsm4(t, sBlo + off);
                    bl[jj * 2][0] = t[0]; bl[jj * 2][1] = t[1];
                    bl[jj * 2 + 1][0] = t[2]; bl[jj * 2 + 1][1] = t[3];
                }
#pragma unroll
                for (int mi = 0; mi < 4; ++mi)
#pragma unroll
                    for (int nj = 0; nj < 4; ++nj) {
                        if (!nj_act[nj]) continue;
                        mma16816(acc[mi][nj], ah[mi], bh[nj]);
                        mma16816(acc[mi][nj], ah[mi], bl[nj]);
                        mma16816(acc[mi][nj], al[mi], bh[nj]);
                    }
            }
        }
    }

    // ---- epilogue via swizzled smem (reuses stage area), coalesced stores
    __syncthreads();
    float* sC = (float*)smem;   // 64 KB < BIAS1_OFF, bias safe
#pragma unroll
    for (int mi = 0; mi < 4; ++mi) {
        const int rl = wm * 64 + mi * 16 + (lane >> 2);
        const int sw = (rl & 7) << 2;
#pragma unroll
        for (int nj = 0; nj < 4; ++nj) {
            const int cl = wn * 32 + nj * 8 + (lane & 3) * 2;
            const int cs = cl ^ sw;
            sC[rl * 128 + cs]           = acc[mi][nj][0];
            sC[rl * 128 + cs + 1]       = acc[mi][nj][1];
            sC[(rl + 8) * 128 + cs]     = acc[mi][nj][2];
            sC[(rl + 8) * 128 + cs + 1] = acc[mi][nj][3];
        }
    }
    __syncthreads();
#pragma unroll 4
    for (int rr = 0; rr < 16; ++rr) {
        const int row = wid + rr * 8;
        const int col = lane * 4;
        const int swr = (row & 7) << 2;
        float4 v = *(const float4*)&sC[row * 128 + (col ^ swr)];
        float4 bb = *(const float4*)&bias_s[col];
        v.x += bb.x; v.y += bb.y; v.z += bb.z; v.w += bb.w;
        *(float4*)(C + (size_t)(m0 + row) * XGS + n0 + col) = v;
    }
}

// ---------------------------------------------------------------------------
// Generic pre-converted bf16 GEMM (GEMM2). R10 design.
// ---------------------------------------------------------------------------
#define MAT_BYTES ABF_BYTES
#define STAGE_BYTES (4 * MAT_BYTES)      // 40960
#define SMEM_BIAS (2 * STAGE_BYTES)
#define SMEM_TOTAL (SMEM_BIAS + 512)     // 82432

__global__ __launch_bounds__(256, 2) void gemm_bf16_nt(
    const __nv_bfloat16* __restrict__ Ahi, const __nv_bfloat16* __restrict__ Alo,
    const __nv_bfloat16* __restrict__ Bhi, const __nv_bfloat16* __restrict__ Blo,
    const float* __restrict__ bias, float* __restrict__ C,
    int ldc, int Nreal, int Kp, int nKC)
{
    extern __shared__ __align__(16) char smem[];
    const uint32_t sbase = smem_u32(smem);
    float* bias_s = (float*)(smem + SMEM_BIAS);

    const int tid  = threadIdx.x;
    const int lane = tid & 31;
    const int wid  = tid >> 5;
    const int wm   = wid & 1;
    const int wn   = wid >> 1;

    const int m0 = blockIdx.x * 128;
    const int n0 = blockIdx.y * 128;

    bool nj_act[4], jj_act[2];
#pragma unroll
    for (int nj = 0; nj < 4; ++nj)
        nj_act[nj] = (n0 + wn * 32 + nj * 8) < Nreal;
    jj_act[0] = nj_act[0] | nj_act[1];
    jj_act[1] = nj_act[2] | nj_act[3];
    const bool warp_act = jj_act[0] | jj_act[1];

    float acc[4][4][4];
#pragma unroll
    for (int i = 0; i < 4; ++i)
#pragma unroll
        for (int j = 0; j < 4; ++j)
#pragma unroll
            for (int q = 0; q < 4; ++q) acc[i][j][q] = 0.f;

    auto issue = [&](int kc, int stage) {
        const uint32_t s32 = sbase + stage * STAGE_BYTES;
#pragma unroll
        for (int i = 0; i < 2; ++i) {
            const int chunk = tid + i * 256;
            const int row = chunk >> 2;
            const int g = chunk & 3;
            const uint32_t dofs = row * LDR80 + g * 16;
            const size_t aofs = (size_t)(m0 + row) * Kp + kc * 32 + g * 8;
            const size_t bofs = (size_t)(n0 + row) * Kp + kc * 32 + g * 8;
            cpasync16(s32 + 0 * MAT_BYTES + dofs, Ahi + aofs);
            cpasync16(s32 + 1 * MAT_BYTES + dofs, Alo + aofs);
            cpasync16(s32 + 2 * MAT_BYTES + dofs, Bhi + bofs);
            cpasync16(s32 + 3 * MAT_BYTES + dofs, Blo + bofs);
        }
    };

    issue(0, 0);
    CP_COMMIT();
    if (tid < 128)
        bias_s[tid] = (n0 + tid < Nreal) ? bias[n0 + tid] : 0.f;

    for (int kc = 0; kc < nKC; ++kc) {
        const int cur = kc & 1;
        CP_WAIT0();
        __syncthreads();

        if (kc + 1 < nKC) {
            issue(kc + 1, cur ^ 1);
            CP_COMMIT();
        }

        const uint32_t sAhi = sbase + cur * STAGE_BYTES;
        const uint32_t sAlo = sAhi + MAT_BYTES;
        const uint32_t sBhi = sAhi + 2 * MAT_BYTES;
        const uint32_t sBlo = sAhi + 3 * MAT_BYTES;

        if (warp_act) {
#pragma unroll
            for (int k16 = 0; k16 < 2; ++k16) {
                const uint32_t kb = k16 * 32;
                uint32_t ah[4][4], al[4][4];
#pragma unroll
                for (int mi = 0; mi < 4; ++mi) {
                    const uint32_t off =
                        (uint32_t)(wm * 64 + mi * 16 + (lane & 15)) * LDR80 +
                        ((lane >> 4) * 16) + kb;
                    ldsm4(ah[mi], sAhi + off);
                    ldsm4(al[mi], sAlo + off);
                }
                uint32_t bh[4][2], bl[4][2];
#pragma unroll
                for (int jj = 0; jj < 2; ++jj) {
                    if (!jj_act[jj]) continue;
                    const uint32_t nrow =
                        (uint32_t)(wn * 32 + jj * 16 + ((lane >> 4) & 1) * 8 +
                                   (lane & 7));
                    const uint32_t off =
                        nrow * LDR80 + (((lane >> 3) & 1) * 16) + kb;
                    uint32_t t[4];
                    ldsm4(t, sBhi + off);
                    bh[jj * 2][0] = t[0]; bh[jj * 2][1] = t[1];
                    bh[jj * 2 + 1][0] = t[2]; bh[jj * 2 + 1][1] = t[3];
                    ldsm4(t, sBlo + off);
                    bl[jj * 2][0] = t[0]; bl[jj * 2][1] = t[1];
                    bl[jj * 2 + 1][0] = t[2]; bl[jj * 2 + 1][1] = t[3];
                }
#pragma unroll
                for (int mi = 0; mi < 4; ++mi)
#pragma unroll
                    for (int nj = 0; nj < 4; ++nj) {
                        if (!nj_act[nj]) continue;
                        mma16816(acc[mi][nj], ah[mi], bh[nj]);
                        mma16816(acc[mi][nj], ah[mi], bl[nj]);
                        mma16816(acc[mi][nj], al[mi], bh[nj]);
                    }
            }
        }
    }

    __syncthreads();
    float* sC = (float*)smem;
#pragma unroll
    for (int mi = 0; mi < 4; ++mi) {
        const int rl = wm * 64 + mi * 16 + (lane >> 2);
        const int sw = (rl & 7) << 2;
#pragma unroll
        for (int nj = 0; nj < 4; ++nj) {
            const int cl = wn * 32 + nj * 8 + (lane & 3) * 2;
            const int cs = cl ^ sw;
            sC[rl * 128 + cs]           = acc[mi][nj][0];
            sC[rl * 128 + cs + 1]       = acc[mi][nj][1];
            sC[(rl + 8) * 128 + cs]     = acc[mi][nj][2];
            sC[(rl + 8) * 128 + cs + 1] = acc[mi][nj][3];
        }
    }
    __syncthreads();

    const bool al4 = ((ldc & 3) == 0);
#pragma unroll 4
    for (int rr = 0; rr < 16; ++rr) {
        const int row = wid + rr * 8;
        const int col = lane * 4;
        const int swr = (row & 7) << 2;
        float4 v = *(const float4*)&sC[row * 128 + (col ^ swr)];
        float4 bb = *(const float4*)&bias_s[col];
        v.x += bb.x; v.y += bb.y; v.z += bb.z; v.w += bb.w;
        float* dst = C + (size_t)(m0 + row) * ldc + n0 + col;
        if (al4) {
            *(float4*)dst = v;
        } else {
            if (n0 + col + 3 < Nreal) {
                dst[0] = v.x; dst[1] = v.y; dst[2] = v.z; dst[3] = v.w;
            } else {
                if (n0 + col + 0 < Nreal) dst[0] = v.x;
                if (n0 + col + 1 < Nreal) dst[1] = v.y;
                if (n0 + col + 2 < Nreal) dst[2] = v.z;
                if (n0 + col + 3 < Nreal) dst[3] = v.w;
            }
        }
    }
}

// ---------------------------------------------------------------------------
// Column-512 GEMV: out[m, 512] = sum_k hs[m,k] * W_out[512,k] + b_out[512]
// ---------------------------------------------------------------------------
__global__ __launch_bounds__(256) void gemv_col512(
    const float* __restrict__ W_out, const float* __restrict__ b_out,
    float* __restrict__ out)
{
    const int gw = (blockIdx.x * 256 + threadIdx.x) >> 5;
    const int lane = threadIdx.x & 31;
    if (gw >= MROWS) return;

    const uint32_t hw = ((const uint32_t*)(g_hshi + (size_t)gw * KP2))[lane];
    const uint32_t lw = ((const uint32_t*)(g_hslo + (size_t)gw * KP2))[lane];
    __nv_bfloat162 h2 = *(const __nv_bfloat162*)&hw;
    __nv_bfloat162 l2 = *(const __nv_bfloat162*)&lw;
    const int k = lane * 2;
    float h0 = __bfloat162float(h2.x) + __bfloat162float(l2.x);
    float h1 = __bfloat162float(h2.y) + __bfloat162float(l2.y);
    float w0 = (k < HH) ? W_out[512 * HH + k] : 0.f;
    float w1 = (k + 1 < HH) ? W_out[512 * HH + k + 1] : 0.f;
    float s = h0 * w0 + h1 * w1;
#pragma unroll
    for (int o = 16; o > 0; o >>= 1)
        s += __shfl_down_sync(0xFFFFFFFFu, s, o);
    if (lane == 0) out[(size_t)gw * FF + 512] = s + b_out[512];
}

// ---------------------------------------------------------------------------
// LSTM scan over batch axis. One block per t (grid 512, 256 threads).
// New structure: ONE barrier per step.
//   threads 0..223: unit u = j>>2 (0..55, 50 real), gate g = j&3.
//     Each computes its gate dot; lane 4u gathers the unit's 4 gates via
//     __shfl_sync and does the cell update into double-buffered h_s.
//   warp 7 (threads 224..255): store crew — writes step b-1's h as bf16
//     hi/lo to global, concurrent with step b's compute.
// xg prefetched 2 steps deep. Fast __expf-based activations.
// ---------------------------------------------------------------------------
__global__ __launch_bounds__(256) void lstm_scan(
    const float* __restrict__ W_hh, const float* __restrict__ b_hh)
{
    __shared__ __align__(16) float h_s[2][56];

    const int t = blockIdx.x;
    const int j = threadIdx.x;
    const int lane = j & 31;
    const int wid = j >> 5;

    const int u = j >> 2;                  // 0..55 for dot threads
    const int g = j & 3;
    const bool dotth = (j < 224);          // warps 0..6
    const bool actth = dotth && (g == 0) && (u < HH);
    const int row = dotth ? (g * HH + ((u < HH) ? u : HH - 1)) : 0;

    float w[HH];
    float bj = 0.f;
    if (dotth) {
#pragma unroll
        for (int k = 0; k < HH; ++k) w[k] = W_hh[row * HH + k];
        bj = b_hh[row];
    }
    float c = 0.f;
    if (j < 56) { h_s[0][j] = 0.f; h_s[1][j] = 0.f; }

    // 2-deep xg prefetch (xg column index == row)
    float pre0 = 0.f, pre1 = 0.f;
    if (dotth && u < HH) {
        pre0 = g_xg[(size_t)t * XGS + row];
        pre1 = g_xg[((size_t)TT + t) * XGS + row];
    }
    __syncthreads();

    for (int b = 0; b < BB; ++b) {
        const int cur = b & 1;
        if (dotth) {
            float g0 = pre0 + bj;
            pre0 = pre1;
            if (b + 2 < BB && u < HH)
                pre1 = g_xg[((size_t)(b + 2) * TT + t) * XGS + row];
            float g1 = 0.f, g2 = 0.f, g3 = 0.f;
#pragma unroll
            for (int k = 0; k < 48; k += 4) {
                float4 hv = *(const float4*)&h_s[cur][k];
                g0 += w[k + 0] * hv.x;
                g1 += w[k + 1] * hv.y;
                g2 += w[k + 2] * hv.z;
                g3 += w[k + 3] * hv.w;
            }
            g0 += w[48] * h_s[cur][48];
            g1 += w[49] * h_s[cur][49];
            float gd = (g0 + g1) + (g2 + g3);

            // gather unit's 4 gates into lane 4u (full-warp shuffles)
            float vf = __shfl_sync(0xFFFFFFFFu, gd, (lane & ~3) | 1);
            float vg = __shfl_sync(0xFFFFFFFFu, gd, (lane & ~3) | 2);
            float vo = __shfl_sync(0xFFFFFFFFu, gd, (lane & ~3) | 3);
            if (actth) {
                float si = sigm_fast(gd);
                float sf = sigm_fast(vf);
                float tg = tanh_fast(vg);
                float so = sigm_fast(vo);
                c = sf * c + si * tg;
                h_s[cur ^ 1][u] = so * tanh_fast(c);
            }
        } else if (wid == 7 && b > 0) {
            // store h of step b-1 (in h_s[cur]) as bf16 hi/lo
            const size_t o = ((size_t)(b - 1) * TT + t) * KP2;
#pragma unroll
            for (int s = 0; s < 2; ++s) {
                const int slot = lane + s * 32;
                float hv = (slot < HH) ? h_s[cur][slot] : 0.f;
                __nv_bfloat16 hh = __float2bfloat16(hv);
                g_hshi[o + slot] = hh;
                g_hslo[o + slot] = __float2bfloat16(hv - __bfloat162float(hh));
            }
        }
        __syncthreads();
    }

    // final step's h lives in h_s[BB & 1] = h_s[0]
    if (wid == 7) {
        const size_t o = ((size_t)(BB - 1) * TT + t) * KP2;
#pragma unroll
        for (int s = 0; s < 2; ++s) {
            const int slot = lane + s * 32;
            float hv = (slot < HH) ? h_s[0][slot] : 0.f;
            __nv_bfloat16 hh = __float2bfloat16(hv);
            g_hshi[o + slot] = hh;
            g_hslo[o + slot] = __float2bfloat16(hv - __bfloat162float(hh));
        }
    }
}

// ---------------------------------------------------------------------------
extern "C" void kernel_launch(void* const* d_in, const int* in_sizes, int n_in,
                              void* d_out, int out_size)
{
    const float* x     = (const float*)d_in[0];
    const float* W_ih  = (const float*)d_in[1];
    const float* W_hh  = (const float*)d_in[2];
    const float* b_ih  = (const float*)d_in[3];
    const float* b_hh  = (const float*)d_in[4];
    const float* W_out = (const float*)d_in[5];
    const float* b_out = (const float*)d_in[6];
    float* out = (float*)d_out;

    float* xg = nullptr;
    __nv_bfloat16 *wihhi, *wihlo, *hshi, *hslo, *wohi, *wolo;
    cudaGetSymbolAddress((void**)&xg, g_xg);
    cudaGetSymbolAddress((void**)&wihhi, g_wihhi);
    cudaGetSymbolAddress((void**)&wihlo, g_wihlo);
    cudaGetSymbolAddress((void**)&hshi, g_hshi);
    cudaGetSymbolAddress((void**)&hslo, g_hslo);
    cudaGetSymbolAddress((void**)&wohi, g_wohi);
    cudaGetSymbolAddress((void**)&wolo, g_wolo);

    cudaFuncSetAttribute(gemm1_fused,
                         cudaFuncAttributeMaxDynamicSharedMemorySize,
                         SMEM1_TOTAL);
    cudaFuncSetAttribute(gemm_bf16_nt,
                         cudaFuncAttributeMaxDynamicSharedMemorySize,
                         SMEM_TOTAL);

    // 0) weight conversions only (tiny)
    conv_w<<<NB_WIH + NB_WO, 256>>>(W_ih, W_out);

    // 1) xg = x @ W_ih^T + b_ih — fused fp32->bf16 conversion in-kernel
    {
        dim3 grid(NP1 / 128, MROWS / 128);   // (2, 256) n-fastest
        gemm1_fused<<<grid, 256, SMEM1_TOTAL>>>(x, wihhi, wihlo, b_ih, xg);
    }
    // 2) LSTM scan (writes hs as bf16 hi/lo)
    lstm_scan<<<TT, 256>>>(W_hh, b_hh);

    // 3) out[:, 0:512] = hs @ W_out[0:512]^T + b_out
    {
        dim3 grid(MROWS / 128, NP2 / 128);   // (256, 4)
        gemm_bf16_nt<<<grid, 256, SMEM_TOTAL>>>(hshi, hslo, wohi, wolo,
                                                b_out, out, FF, NP2, KP2, NKC2);
    }
    // 3b) out[:, 512] via warp-per-row GEMV
    gemv_col512<<<MROWS / 8, 256>>>(W_out, b_out, out);
}